// round 1
// baseline (speedup 1.0000x reference)
#include <cuda_runtime.h>
#include <math.h>

// Problem constants
#define B_SZ 2
#define L_SZ 2048
#define D_SZ 4096
#define H_N  32
#define HD_S 128
#define M_ROWS (B_SZ * L_SZ)   // 4096

// Scratch buffers (device globals: allocation-free per harness rules)
__device__ float g_Q[(size_t)M_ROWS * D_SZ];
__device__ float g_K[(size_t)M_ROWS * D_SZ];
__device__ float g_V[(size_t)M_ROWS * D_SZ];
__device__ float g_A[(size_t)M_ROWS * D_SZ];

// ---------------------------------------------------------------------------
// SGEMM: C[M,N] = A[M,K] * Bm[N,K]^T   (both row-major, K contiguous)
// 128x128 block tile, BK=8, 256 threads, 8x8 microtile (split 4+4)
// ---------------------------------------------------------------------------
__global__ __launch_bounds__(256) void sgemm_nt(const float* __restrict__ A,
                                                const float* __restrict__ Bm,
                                                float* __restrict__ C,
                                                int M, int N, int K)
{
    const int BM = 128, BN = 128, BK = 8;
    __shared__ __align__(16) float As[BK][BM + 4];  // stride 132 floats (16B-aligned rows)
    __shared__ __align__(16) float Bs[BK][BN + 4];

    int tid = threadIdx.x;
    int tx = tid & 15;
    int ty = tid >> 4;
    int bm = blockIdx.y * BM;
    int bn = blockIdx.x * BN;

    int lr = tid >> 1;        // 0..127 tile row for loads
    int lk = (tid & 1) * 4;   // 0 or 4

    const float* Aptr = A + (size_t)(bm + lr) * K + lk;
    const float* Bptr = Bm + (size_t)(bn + lr) * K + lk;

    float acc[8][8];
#pragma unroll
    for (int i = 0; i < 8; i++)
#pragma unroll
        for (int j = 0; j < 8; j++) acc[i][j] = 0.0f;

    for (int k0 = 0; k0 < K; k0 += BK) {
        float4 av = *(const float4*)(Aptr + k0);
        float4 bv = *(const float4*)(Bptr + k0);
        __syncthreads();
        As[lk + 0][lr] = av.x; As[lk + 1][lr] = av.y;
        As[lk + 2][lr] = av.z; As[lk + 3][lr] = av.w;
        Bs[lk + 0][lr] = bv.x; Bs[lk + 1][lr] = bv.y;
        Bs[lk + 2][lr] = bv.z; Bs[lk + 3][lr] = bv.w;
        __syncthreads();

#pragma unroll
        for (int kk = 0; kk < BK; kk++) {
            float4 a0 = *(const float4*)&As[kk][ty * 4];
            float4 a1 = *(const float4*)&As[kk][64 + ty * 4];
            float4 b0 = *(const float4*)&Bs[kk][tx * 4];
            float4 b1 = *(const float4*)&Bs[kk][64 + tx * 4];
            float a[8] = {a0.x, a0.y, a0.z, a0.w, a1.x, a1.y, a1.z, a1.w};
            float b[8] = {b0.x, b0.y, b0.z, b0.w, b1.x, b1.y, b1.z, b1.w};
#pragma unroll
            for (int i = 0; i < 8; i++)
#pragma unroll
                for (int j = 0; j < 8; j++) acc[i][j] += a[i] * b[j];
        }
    }

#pragma unroll
    for (int i = 0; i < 8; i++) {
        int row = bm + ((i < 4) ? (ty * 4 + i) : (64 + ty * 4 + (i - 4)));
        float4 c0 = make_float4(acc[i][0], acc[i][1], acc[i][2], acc[i][3]);
        float4 c1 = make_float4(acc[i][4], acc[i][5], acc[i][6], acc[i][7]);
        *(float4*)(C + (size_t)row * N + bn + tx * 4)      = c0;
        *(float4*)(C + (size_t)row * N + bn + 64 + tx * 4) = c1;
    }
}

// ---------------------------------------------------------------------------
// RoPE (interleaved pairs) + optional scale (used to fold 1/sqrt(HD) into Q)
// One thread per (row, head, pair). t layout: [M_ROWS][D] with D = H*HD.
// ---------------------------------------------------------------------------
__global__ void rope_kernel(float2* __restrict__ t,
                            const float* __restrict__ fcos,
                            const float* __restrict__ fsin,
                            float scale)
{
    int idx = blockIdx.x * blockDim.x + threadIdx.x;   // pair index
    const int pairs = M_ROWS * D_SZ / 2;
    if (idx >= pairs) return;
    int i = idx & (HD_S / 2 - 1);              // pair index within head (0..63)
    int l = (idx / (D_SZ / 2)) % L_SZ;         // sequence position
    float c = fcos[l * (HD_S / 2) + i];
    float s = fsin[l * (HD_S / 2) + i];
    float2 v = t[idx];
    float2 o;
    o.x = (v.x * c - v.y * s) * scale;
    o.y = (v.x * s + v.y * c) * scale;
    t[idx] = o;
}

// ---------------------------------------------------------------------------
// Flash attention (fp32). Per block: one (b,h) and a 64-row Q tile.
// Online softmax over 64-row KV tiles. 256 threads = 16x16 grid.
// Thread (ty,tx): S rows 4ty..4ty+3, S cols tx+16*jj ; O cols tx+16*c (c<8).
// ---------------------------------------------------------------------------
#define QT 64
#define KT 64
#define QS_STRIDE 129
#define KT_STRIDE 65
#define PS_STRIDE 65

__global__ __launch_bounds__(256) void attn_kernel(const float* __restrict__ Q,
                                                   const float* __restrict__ Kg,
                                                   const float* __restrict__ Vg,
                                                   float* __restrict__ Og)
{
    extern __shared__ float sm[];
    float* Qs = sm;                                 // [64][129]
    float* Kt = Qs + QT * QS_STRIDE;                // [128][65]  (transposed K)
    float* Vs = Kt + HD_S * KT_STRIDE;              // [64][128]
    float* Ps = Vs + KT * HD_S;                     // [64][65]

    int tid = threadIdx.x;
    int tx = tid & 15;
    int ty = tid >> 4;
    int bh = blockIdx.y;
    int b = bh / H_N, h = bh % H_N;
    int q0 = blockIdx.x * QT;
    const size_t rowbase = (size_t)b * L_SZ;
    const size_t colbase = (size_t)h * HD_S;

    // Load Q tile (coalesced gmem, conflict-free compute reads via stride 129)
    for (int idx = tid; idx < QT * HD_S; idx += 256) {
        int r = idx >> 7, d = idx & 127;
        Qs[r * QS_STRIDE + d] = Q[(rowbase + q0 + r) * D_SZ + colbase + d];
    }

    float mrow[4], lsum[4], o[4][8];
#pragma unroll
    for (int i = 0; i < 4; i++) {
        mrow[i] = -1e30f;
        lsum[i] = 0.0f;
#pragma unroll
        for (int c = 0; c < 8; c++) o[i][c] = 0.0f;
    }

    for (int kv0 = 0; kv0 < L_SZ; kv0 += KT) {
        __syncthreads();  // protect Kt/Vs/Ps against previous iteration's readers

        // K tile, stored transposed: Kt[d][j] (smem stores conflict-free: stride 65)
        for (int idx = tid; idx < KT * HD_S; idx += 256) {
            int j = idx >> 7, d = idx & 127;
            Kt[d * KT_STRIDE + j] = Kg[(rowbase + kv0 + j) * D_SZ + colbase + d];
        }
        // V tile, row-major, float4 both sides
        for (int idx = tid; idx < KT * HD_S / 4; idx += 256) {
            int j = idx >> 5, dq = idx & 31;
            *(float4*)&Vs[j * HD_S + dq * 4] =
                *(const float4*)&Vg[(rowbase + kv0 + j) * D_SZ + colbase + dq * 4];
        }
        __syncthreads();

        // --- S = Q K^T (scale pre-folded into Q) ---
        float s[4][4];
#pragma unroll
        for (int i = 0; i < 4; i++)
#pragma unroll
            for (int jj = 0; jj < 4; jj++) s[i][jj] = 0.0f;

#pragma unroll 4
        for (int d = 0; d < HD_S; d++) {
            float a0 = Qs[(4 * ty + 0) * QS_STRIDE + d];
            float a1 = Qs[(4 * ty + 1) * QS_STRIDE + d];
            float a2 = Qs[(4 * ty + 2) * QS_STRIDE + d];
            float a3 = Qs[(4 * ty + 3) * QS_STRIDE + d];
            const float* kd = &Kt[d * KT_STRIDE + tx];
            float b0 = kd[0], b1 = kd[16], b2 = kd[32], b3 = kd[48];
            s[0][0] += a0 * b0; s[0][1] += a0 * b1; s[0][2] += a0 * b2; s[0][3] += a0 * b3;
            s[1][0] += a1 * b0; s[1][1] += a1 * b1; s[1][2] += a1 * b2; s[1][3] += a1 * b3;
            s[2][0] += a2 * b0; s[2][1] += a2 * b1; s[2][2] += a2 * b2; s[2][3] += a2 * b3;
            s[3][0] += a3 * b0; s[3][1] += a3 * b1; s[3][2] += a3 * b2; s[3][3] += a3 * b3;
        }

        // --- online softmax (row groups of 16 lanes; shfl width 16) ---
#pragma unroll
        for (int i = 0; i < 4; i++) {
            float tm = fmaxf(fmaxf(s[i][0], s[i][1]), fmaxf(s[i][2], s[i][3]));
#pragma unroll
            for (int off = 8; off > 0; off >>= 1)
                tm = fmaxf(tm, __shfl_xor_sync(0xffffffffu, tm, off, 16));
            float mnew = fmaxf(mrow[i], tm);
            float corr = __expf(mrow[i] - mnew);
            float rs = 0.0f;
#pragma unroll
            for (int jj = 0; jj < 4; jj++) {
                float p = __expf(s[i][jj] - mnew);
                s[i][jj] = p;
                rs += p;
            }
#pragma unroll
            for (int off = 8; off > 0; off >>= 1)
                rs += __shfl_xor_sync(0xffffffffu, rs, off, 16);
            lsum[i] = lsum[i] * corr + rs;
            mrow[i] = mnew;
#pragma unroll
            for (int c = 0; c < 8; c++) o[i][c] *= corr;
#pragma unroll
            for (int jj = 0; jj < 4; jj++)
                Ps[(4 * ty + i) * PS_STRIDE + tx + 16 * jj] = s[i][jj];
        }
        __syncthreads();

        // --- O += P V ---
#pragma unroll 2
        for (int j = 0; j < KT; j++) {
            float p0 = Ps[(4 * ty + 0) * PS_STRIDE + j];
            float p1 = Ps[(4 * ty + 1) * PS_STRIDE + j];
            float p2 = Ps[(4 * ty + 2) * PS_STRIDE + j];
            float p3 = Ps[(4 * ty + 3) * PS_STRIDE + j];
            const float* vr = &Vs[j * HD_S + tx];
#pragma unroll
            for (int c = 0; c < 8; c++) {
                float v = vr[16 * c];
                o[0][c] += p0 * v;
                o[1][c] += p1 * v;
                o[2][c] += p2 * v;
                o[3][c] += p3 * v;
            }
        }
    }

    // write back, layout [B*L][D] (same as Q) so the Wo GEMM consumes directly
#pragma unroll
    for (int i = 0; i < 4; i++) {
        float inv = 1.0f / lsum[i];
        size_t base = (rowbase + q0 + 4 * ty + i) * D_SZ + colbase + tx;
#pragma unroll
        for (int c = 0; c < 8; c++) Og[base + 16 * c] = o[i][c] * inv;
    }
}

// ---------------------------------------------------------------------------
// Launch
// ---------------------------------------------------------------------------
extern "C" void kernel_launch(void* const* d_in, const int* in_sizes, int n_in,
                              void* d_out, int out_size)
{
    (void)in_sizes; (void)n_in; (void)out_size;
    const float* x    = (const float*)d_in[0];
    const float* fcos = (const float*)d_in[1];
    const float* fsin = (const float*)d_in[2];
    const float* Wq   = (const float*)d_in[3];
    const float* Wk   = (const float*)d_in[4];
    const float* Wv   = (const float*)d_in[5];
    const float* Wo   = (const float*)d_in[6];
    float* out = (float*)d_out;

    float *Qb, *Kb, *Vb, *Ab;
    cudaGetSymbolAddress((void**)&Qb, g_Q);
    cudaGetSymbolAddress((void**)&Kb, g_K);
    cudaGetSymbolAddress((void**)&Vb, g_V);
    cudaGetSymbolAddress((void**)&Ab, g_A);

    dim3 gg(D_SZ / 128, M_ROWS / 128);

    sgemm_nt<<<gg, 256>>>(x, Wq, Qb, M_ROWS, D_SZ, D_SZ);
    sgemm_nt<<<gg, 256>>>(x, Wk, Kb, M_ROWS, D_SZ, D_SZ);
    sgemm_nt<<<gg, 256>>>(x, Wv, Vb, M_ROWS, D_SZ, D_SZ);

    const int pairs = M_ROWS * D_SZ / 2;
    const float qscale = 0.08838834764831845f;  // 1/sqrt(128)
    rope_kernel<<<(pairs + 255) / 256, 256>>>((float2*)Qb, fcos, fsin, qscale);
    rope_kernel<<<(pairs + 255) / 256, 256>>>((float2*)Kb, fcos, fsin, 1.0f);

    const size_t ATT_SMEM =
        (QT * QS_STRIDE + HD_S * KT_STRIDE + KT * HD_S + QT * PS_STRIDE) * sizeof(float);
    cudaFuncSetAttribute(attn_kernel, cudaFuncAttributeMaxDynamicSharedMemorySize,
                         (int)ATT_SMEM);
    attn_kernel<<<dim3(L_SZ / QT, B_SZ * H_N), 256, ATT_SMEM>>>(Qb, Kb, Vb, Ab);

    sgemm_nt<<<gg, 256>>>(Ab, Wo, out, M_ROWS, D_SZ, D_SZ);
}

// round 4
// speedup vs baseline: 2.1605x; 2.1605x over previous
#include <cuda_runtime.h>
#include <cstdint>
#include <math.h>

// Problem constants
#define B_SZ 2
#define L_SZ 2048
#define D_SZ 4096
#define H_N  32
#define HD_S 128
#define M_ROWS (B_SZ * L_SZ)   // 4096

// ---------------------------------------------------------------------------
// Scratch (device globals: allocation-free per harness rules)
// ---------------------------------------------------------------------------
__device__ __align__(256) float g_Q[(size_t)M_ROWS * D_SZ];
__device__ __align__(256) float g_K[(size_t)M_ROWS * D_SZ];
__device__ __align__(256) float g_V[(size_t)M_ROWS * D_SZ];
__device__ __align__(256) float g_A[(size_t)M_ROWS * D_SZ];
__device__ __align__(256) float g_Xc[(size_t)M_ROWS * D_SZ];  // tf32-rounded act
__device__ __align__(256) float g_Wc[(size_t)D_SZ * D_SZ];    // tf32-rounded weight

// ---------------------------------------------------------------------------
// Helpers
// ---------------------------------------------------------------------------
__device__ __forceinline__ uint32_t smem_u32(const void* p) {
    uint32_t a;
    asm("{ .reg .u64 t; cvta.to.shared.u64 t, %1; cvt.u32.u64 %0, t; }"
        : "=r"(a) : "l"(p));
    return a;
}
__device__ __forceinline__ void cp16(uint32_t saddr, const void* gaddr) {
    asm volatile("cp.async.cg.shared.global [%0], [%1], 16;" :: "r"(saddr), "l"(gaddr));
}
__device__ __forceinline__ void mma_tf32(float& c0, float& c1, float& c2, float& c3,
                                         uint32_t a0, uint32_t a1, uint32_t a2, uint32_t a3,
                                         uint32_t b0, uint32_t b1) {
    asm volatile(
        "mma.sync.aligned.m16n8k8.row.col.f32.tf32.tf32.f32 "
        "{%0,%1,%2,%3}, {%4,%5,%6,%7}, {%8,%9}, {%0,%1,%2,%3};"
        : "+f"(c0), "+f"(c1), "+f"(c2), "+f"(c3)
        : "r"(a0), "r"(a1), "r"(a2), "r"(a3), "r"(b0), "r"(b1));
}

// ---------------------------------------------------------------------------
// tf32 rounding pass (RN; avoids truncation bias of feeding raw fp32 to HMMA)
// ---------------------------------------------------------------------------
__device__ __forceinline__ float to_tf32(float f) {
    uint32_t o;
    asm("cvt.rna.tf32.f32 %0, %1;" : "=r"(o) : "f"(f));
    return __uint_as_float(o);
}
__global__ void cvt_tf32_kernel(const float4* __restrict__ in, float4* __restrict__ out, int n4) {
    int i = blockIdx.x * blockDim.x + threadIdx.x;
    if (i >= n4) return;
    float4 v = in[i];
    v.x = to_tf32(v.x); v.y = to_tf32(v.y); v.z = to_tf32(v.z); v.w = to_tf32(v.w);
    out[i] = v;
}

// ---------------------------------------------------------------------------
// tf32 tensor-core GEMM via mma.sync (target-independent PTX, works on sm_100):
//   C[4096,4096] = A[4096,4096] * Bw[4096,4096]^T   (row-major, K contiguous)
// 128x128 CTA tile, BK=32, 8 warps (2x4), 64x32 warp tile, 2-stage cp.async.
// Smem stride 36 floats -> conflict-free fragment LDS.
// ---------------------------------------------------------------------------
#define SSTRIDE 36
#define SSZ (128 * SSTRIDE)          // floats per tile stage
#define NCHUNK (D_SZ / 32)           // 128

__global__ __launch_bounds__(256, 2) void gemm_tf32(const float* __restrict__ A,
                                                    const float* __restrict__ Bw,
                                                    float* __restrict__ C)
{
    extern __shared__ float sm[];
    const uint32_t smb = smem_u32(sm);
    const int tid = threadIdx.x;
    const int lane = tid & 31, wid = tid >> 5;
    const int warp_m = wid >> 2, warp_n = wid & 3;
    const int grp = lane >> 2, qid = lane & 3;

    const float* Ag = A + (size_t)(blockIdx.y * 128) * D_SZ;
    const float* Bg = Bw + (size_t)(blockIdx.x * 128) * D_SZ;

    // per-thread load coords: 4 x 16B units per tile
    const int lrow = tid >> 3;        // 0..31, +32 per i (u>>3 with u=tid+256i: rows stride 32)
    const int lc = tid & 7;           // 16B unit in row

    auto issue_stage = [&](int it, int s) {
        const int k0 = it * 32;
        const uint32_t base = smb + (uint32_t)s * 2 * SSZ * 4;
#pragma unroll
        for (int i = 0; i < 4; i++) {
            const int row = lrow + 32 * i;
            const uint32_t off = (uint32_t)(row * SSTRIDE + lc * 4) * 4;
            cp16(base + off, Ag + (size_t)row * D_SZ + k0 + lc * 4);
            cp16(base + (uint32_t)SSZ * 4 + off, Bg + (size_t)row * D_SZ + k0 + lc * 4);
        }
        asm volatile("cp.async.commit_group;" ::: "memory");
    };

    float acc[4][4][4];
#pragma unroll
    for (int mi = 0; mi < 4; mi++)
#pragma unroll
        for (int ni = 0; ni < 4; ni++)
#pragma unroll
            for (int r = 0; r < 4; r++) acc[mi][ni][r] = 0.0f;

    issue_stage(0, 0);

    const int ar0 = warp_m * 64 + grp;
    const int bn0 = warp_n * 32 + grp;

    for (int it = 0; it < NCHUNK; ++it) {
        if (it + 1 < NCHUNK) issue_stage(it + 1, (it + 1) & 1);
        else asm volatile("cp.async.commit_group;" ::: "memory");
        asm volatile("cp.async.wait_group 1;" ::: "memory");
        __syncthreads();

        const uint32_t* Au = (const uint32_t*)(sm + (it & 1) * 2 * SSZ);
        const uint32_t* Bu = Au + SSZ;

#pragma unroll
        for (int ks = 0; ks < 4; ks++) {
            const int kc = ks * 8 + qid;
            uint32_t a[4][4], b[4][2];
#pragma unroll
            for (int mi = 0; mi < 4; mi++) {
                const int r = ar0 + mi * 16;
                a[mi][0] = Au[r * SSTRIDE + kc];
                a[mi][1] = Au[(r + 8) * SSTRIDE + kc];
                a[mi][2] = Au[r * SSTRIDE + kc + 4];
                a[mi][3] = Au[(r + 8) * SSTRIDE + kc + 4];
            }
#pragma unroll
            for (int ni = 0; ni < 4; ni++) {
                const int n = bn0 + ni * 8;
                b[ni][0] = Bu[n * SSTRIDE + kc];
                b[ni][1] = Bu[n * SSTRIDE + kc + 4];
            }
#pragma unroll
            for (int mi = 0; mi < 4; mi++)
#pragma unroll
                for (int ni = 0; ni < 4; ni++)
                    mma_tf32(acc[mi][ni][0], acc[mi][ni][1], acc[mi][ni][2], acc[mi][ni][3],
                             a[mi][0], a[mi][1], a[mi][2], a[mi][3],
                             b[ni][0], b[ni][1]);
        }
        __syncthreads();
    }

    // Epilogue: fragment rows = base+grp (+8), cols = qid*2 (+1)
#pragma unroll
    for (int mi = 0; mi < 4; mi++) {
        const int row = blockIdx.y * 128 + warp_m * 64 + mi * 16 + grp;
#pragma unroll
        for (int ni = 0; ni < 4; ni++) {
            const int col = blockIdx.x * 128 + warp_n * 32 + ni * 8 + qid * 2;
            *(float2*)&C[(size_t)row * D_SZ + col] =
                make_float2(acc[mi][ni][0], acc[mi][ni][1]);
            *(float2*)&C[(size_t)(row + 8) * D_SZ + col] =
                make_float2(acc[mi][ni][2], acc[mi][ni][3]);
        }
    }
}

// ---------------------------------------------------------------------------
// RoPE (interleaved pairs) + optional scale folded into Q
// ---------------------------------------------------------------------------
__global__ void rope_kernel(float2* __restrict__ t,
                            const float* __restrict__ fcos,
                            const float* __restrict__ fsin,
                            float scale)
{
    int idx = blockIdx.x * blockDim.x + threadIdx.x;
    const int pairs = M_ROWS * D_SZ / 2;
    if (idx >= pairs) return;
    int i = idx & (HD_S / 2 - 1);
    int l = (idx / (D_SZ / 2)) % L_SZ;
    float c = fcos[l * (HD_S / 2) + i];
    float s = fsin[l * (HD_S / 2) + i];
    float2 v = t[idx];
    float2 o;
    o.x = (v.x * c - v.y * s) * scale;
    o.y = (v.x * s + v.y * c) * scale;
    t[idx] = o;
}

// ---------------------------------------------------------------------------
// Flash attention (fp32 SIMT, unchanged)
// ---------------------------------------------------------------------------
#define QT 64
#define KT 64
#define QS_STRIDE 129
#define KT_STRIDE 65
#define PS_STRIDE 65

__global__ __launch_bounds__(256) void attn_kernel(const float* __restrict__ Q,
                                                   const float* __restrict__ Kg,
                                                   const float* __restrict__ Vg,
                                                   float* __restrict__ Og)
{
    extern __shared__ float smf[];
    float* Qs = smf;
    float* Kt = Qs + QT * QS_STRIDE;
    float* Vs = Kt + HD_S * KT_STRIDE;
    float* Ps = Vs + KT * HD_S;

    int tid = threadIdx.x;
    int tx = tid & 15;
    int ty = tid >> 4;
    int bh = blockIdx.y;
    int b = bh / H_N, h = bh % H_N;
    int q0 = blockIdx.x * QT;
    const size_t rowbase = (size_t)b * L_SZ;
    const size_t colbase = (size_t)h * HD_S;

    for (int idx = tid; idx < QT * HD_S; idx += 256) {
        int r = idx >> 7, d = idx & 127;
        Qs[r * QS_STRIDE + d] = Q[(rowbase + q0 + r) * D_SZ + colbase + d];
    }

    float mrow[4], lsum[4], o[4][8];
#pragma unroll
    for (int i = 0; i < 4; i++) {
        mrow[i] = -1e30f; lsum[i] = 0.0f;
#pragma unroll
        for (int c = 0; c < 8; c++) o[i][c] = 0.0f;
    }

    for (int kv0 = 0; kv0 < L_SZ; kv0 += KT) {
        __syncthreads();
        for (int idx = tid; idx < KT * HD_S; idx += 256) {
            int j = idx >> 7, d = idx & 127;
            Kt[d * KT_STRIDE + j] = Kg[(rowbase + kv0 + j) * D_SZ + colbase + d];
        }
        for (int idx = tid; idx < KT * HD_S / 4; idx += 256) {
            int j = idx >> 5, dq = idx & 31;
            *(float4*)&Vs[j * HD_S + dq * 4] =
                *(const float4*)&Vg[(rowbase + kv0 + j) * D_SZ + colbase + dq * 4];
        }
        __syncthreads();

        float s4[4][4];
#pragma unroll
        for (int i = 0; i < 4; i++)
#pragma unroll
            for (int jj = 0; jj < 4; jj++) s4[i][jj] = 0.0f;

#pragma unroll 4
        for (int d = 0; d < HD_S; d++) {
            float a0 = Qs[(4 * ty + 0) * QS_STRIDE + d];
            float a1 = Qs[(4 * ty + 1) * QS_STRIDE + d];
            float a2 = Qs[(4 * ty + 2) * QS_STRIDE + d];
            float a3 = Qs[(4 * ty + 3) * QS_STRIDE + d];
            const float* kd = &Kt[d * KT_STRIDE + tx];
            float b0 = kd[0], b1 = kd[16], b2 = kd[32], b3 = kd[48];
            s4[0][0] += a0 * b0; s4[0][1] += a0 * b1; s4[0][2] += a0 * b2; s4[0][3] += a0 * b3;
            s4[1][0] += a1 * b0; s4[1][1] += a1 * b1; s4[1][2] += a1 * b2; s4[1][3] += a1 * b3;
            s4[2][0] += a2 * b0; s4[2][1] += a2 * b1; s4[2][2] += a2 * b2; s4[2][3] += a2 * b3;
            s4[3][0] += a3 * b0; s4[3][1] += a3 * b1; s4[3][2] += a3 * b2; s4[3][3] += a3 * b3;
        }

#pragma unroll
        for (int i = 0; i < 4; i++) {
            float tm = fmaxf(fmaxf(s4[i][0], s4[i][1]), fmaxf(s4[i][2], s4[i][3]));
#pragma unroll
            for (int off = 8; off > 0; off >>= 1)
                tm = fmaxf(tm, __shfl_xor_sync(0xffffffffu, tm, off, 16));
            float mnew = fmaxf(mrow[i], tm);
            float corr = __expf(mrow[i] - mnew);
            float rs = 0.0f;
#pragma unroll
            for (int jj = 0; jj < 4; jj++) {
                float p = __expf(s4[i][jj] - mnew);
                s4[i][jj] = p;
                rs += p;
            }
#pragma unroll
            for (int off = 8; off > 0; off >>= 1)
                rs += __shfl_xor_sync(0xffffffffu, rs, off, 16);
            lsum[i] = lsum[i] * corr + rs;
            mrow[i] = mnew;
#pragma unroll
            for (int c = 0; c < 8; c++) o[i][c] *= corr;
#pragma unroll
            for (int jj = 0; jj < 4; jj++)
                Ps[(4 * ty + i) * PS_STRIDE + tx + 16 * jj] = s4[i][jj];
        }
        __syncthreads();

#pragma unroll 2
        for (int j = 0; j < KT; j++) {
            float p0 = Ps[(4 * ty + 0) * PS_STRIDE + j];
            float p1 = Ps[(4 * ty + 1) * PS_STRIDE + j];
            float p2 = Ps[(4 * ty + 2) * PS_STRIDE + j];
            float p3 = Ps[(4 * ty + 3) * PS_STRIDE + j];
            const float* vr = &Vs[j * HD_S + tx];
#pragma unroll
            for (int c = 0; c < 8; c++) {
                float v = vr[16 * c];
                o[0][c] += p0 * v;
                o[1][c] += p1 * v;
                o[2][c] += p2 * v;
                o[3][c] += p3 * v;
            }
        }
    }

#pragma unroll
    for (int i = 0; i < 4; i++) {
        float inv = 1.0f / lsum[i];
        size_t base = (rowbase + q0 + 4 * ty + i) * D_SZ + colbase + tx;
#pragma unroll
        for (int c = 0; c < 8; c++) Og[base + 16 * c] = o[i][c] * inv;
    }
}

// ---------------------------------------------------------------------------
// Launch
// ---------------------------------------------------------------------------
extern "C" void kernel_launch(void* const* d_in, const int* in_sizes, int n_in,
                              void* d_out, int out_size)
{
    (void)in_sizes; (void)n_in; (void)out_size;
    const float* x    = (const float*)d_in[0];
    const float* fcos = (const float*)d_in[1];
    const float* fsin = (const float*)d_in[2];
    const float* Wq   = (const float*)d_in[3];
    const float* Wk   = (const float*)d_in[4];
    const float* Wv   = (const float*)d_in[5];
    const float* Wo   = (const float*)d_in[6];
    float* out = (float*)d_out;

    float *Qb, *Kb, *Vb, *Ab, *Xc, *Wc;
    cudaGetSymbolAddress((void**)&Qb, g_Q);
    cudaGetSymbolAddress((void**)&Kb, g_K);
    cudaGetSymbolAddress((void**)&Vb, g_V);
    cudaGetSymbolAddress((void**)&Ab, g_A);
    cudaGetSymbolAddress((void**)&Xc, g_Xc);
    cudaGetSymbolAddress((void**)&Wc, g_Wc);

    const int n4 = M_ROWS * D_SZ / 4;
    const int CVB = 256, CVG = (n4 + CVB - 1) / CVB;

    const size_t GEMM_SMEM = (size_t)2 * 2 * SSZ * sizeof(float);   // 73728 B
    const size_t ATT_SMEM =
        (QT * QS_STRIDE + HD_S * KT_STRIDE + KT * HD_S + QT * PS_STRIDE) * sizeof(float);
    cudaFuncSetAttribute(gemm_tf32, cudaFuncAttributeMaxDynamicSharedMemorySize,
                         (int)GEMM_SMEM);
    cudaFuncSetAttribute(attn_kernel, cudaFuncAttributeMaxDynamicSharedMemorySize,
                         (int)ATT_SMEM);

    dim3 gg(D_SZ / 128, M_ROWS / 128);

    // round activations + weights to tf32 (RN), then tensor-core GEMMs
    cvt_tf32_kernel<<<CVG, CVB>>>((const float4*)x, (float4*)Xc, n4);
    cvt_tf32_kernel<<<CVG, CVB>>>((const float4*)Wq, (float4*)Wc, n4);
    gemm_tf32<<<gg, 256, GEMM_SMEM>>>(Xc, Wc, Qb);
    cvt_tf32_kernel<<<CVG, CVB>>>((const float4*)Wk, (float4*)Wc, n4);
    gemm_tf32<<<gg, 256, GEMM_SMEM>>>(Xc, Wc, Kb);
    cvt_tf32_kernel<<<CVG, CVB>>>((const float4*)Wv, (float4*)Wc, n4);
    gemm_tf32<<<gg, 256, GEMM_SMEM>>>(Xc, Wc, Vb);

    const int pairs = M_ROWS * D_SZ / 2;
    const float qscale = 0.08838834764831845f;  // 1/sqrt(128)
    rope_kernel<<<(pairs + 255) / 256, 256>>>((float2*)Qb, fcos, fsin, qscale);
    rope_kernel<<<(pairs + 255) / 256, 256>>>((float2*)Kb, fcos, fsin, 1.0f);

    attn_kernel<<<dim3(L_SZ / QT, B_SZ * H_N), 256, ATT_SMEM>>>(Qb, Kb, Vb, Ab);

    cvt_tf32_kernel<<<CVG, CVB>>>((const float4*)Ab, (float4*)Xc, n4);
    cvt_tf32_kernel<<<CVG, CVB>>>((const float4*)Wo, (float4*)Wc, n4);
    gemm_tf32<<<gg, 256, GEMM_SMEM>>>(Xc, Wc, out);
}

// round 6
// speedup vs baseline: 3.5690x; 1.6519x over previous
#include <cuda_runtime.h>
#include <cstdint>
#include <math.h>

// Problem constants
#define B_SZ 2
#define L_SZ 2048
#define D_SZ 4096
#define H_N  32
#define HD_S 128
#define M_ROWS (B_SZ * L_SZ)   // 4096

// ---------------------------------------------------------------------------
// Scratch (device globals: allocation-free per harness rules)
// ---------------------------------------------------------------------------
__device__ __align__(256) float g_Q[(size_t)M_ROWS * D_SZ];
__device__ __align__(256) float g_K[(size_t)M_ROWS * D_SZ];
__device__ __align__(256) float g_V[(size_t)M_ROWS * D_SZ];
__device__ __align__(256) float g_A[(size_t)M_ROWS * D_SZ];
__device__ __align__(256) float g_Xc[(size_t)M_ROWS * D_SZ];
__device__ __align__(256) float g_Wqc[(size_t)D_SZ * D_SZ];
__device__ __align__(256) float g_Wkc[(size_t)D_SZ * D_SZ];
__device__ __align__(256) float g_Wvc[(size_t)D_SZ * D_SZ];
__device__ __align__(256) float g_Woc[(size_t)D_SZ * D_SZ];

// ---------------------------------------------------------------------------
// Helpers
// ---------------------------------------------------------------------------
__device__ __forceinline__ uint32_t smem_u32(const void* p) {
    uint32_t a;
    asm("{ .reg .u64 t; cvta.to.shared.u64 t, %1; cvt.u32.u64 %0, t; }"
        : "=r"(a) : "l"(p));
    return a;
}
__device__ __forceinline__ void cp16(uint32_t saddr, const void* gaddr) {
    asm volatile("cp.async.cg.shared.global [%0], [%1], 16;" :: "r"(saddr), "l"(gaddr));
}
__device__ __forceinline__ void mma_tf32(float& c0, float& c1, float& c2, float& c3,
                                         uint32_t a0, uint32_t a1, uint32_t a2, uint32_t a3,
                                         uint32_t b0, uint32_t b1) {
    asm volatile(
        "mma.sync.aligned.m16n8k8.row.col.f32.tf32.tf32.f32 "
        "{%0,%1,%2,%3}, {%4,%5,%6,%7}, {%8,%9}, {%0,%1,%2,%3};"
        : "+f"(c0), "+f"(c1), "+f"(c2), "+f"(c3)
        : "r"(a0), "r"(a1), "r"(a2), "r"(a3), "r"(b0), "r"(b1));
}
__device__ __forceinline__ float to_tf32(float f) {
    uint32_t o;
    asm("cvt.rna.tf32.f32 %0, %1;" : "=r"(o) : "f"(f));
    return __uint_as_float(o);
}
__device__ __forceinline__ uint32_t fu(float f) { return __float_as_uint(f); }

__global__ void cvt_tf32_kernel(const float4* __restrict__ in, float4* __restrict__ out, int n4) {
    int i = blockIdx.x * blockDim.x + threadIdx.x;
    if (i >= n4) return;
    float4 v = in[i];
    v.x = to_tf32(v.x); v.y = to_tf32(v.y); v.z = to_tf32(v.z); v.w = to_tf32(v.w);
    out[i] = v;
}

// ---------------------------------------------------------------------------
// tf32 GEMM via mma.sync: C = A * Bw^T  (row-major, K contiguous), as in R4
// ---------------------------------------------------------------------------
#define SSTRIDE 36
#define SSZ (128 * SSTRIDE)
#define NCHUNK (D_SZ / 32)

__global__ __launch_bounds__(256, 2) void gemm_tf32(const float* __restrict__ A,
                                                    const float* __restrict__ Bw,
                                                    float* __restrict__ C)
{
    extern __shared__ float sm[];
    const uint32_t smb = smem_u32(sm);
    const int tid = threadIdx.x;
    const int lane = tid & 31, wid = tid >> 5;
    const int warp_m = wid >> 2, warp_n = wid & 3;
    const int grp = lane >> 2, qid = lane & 3;

    const float* Ag = A + (size_t)(blockIdx.y * 128) * D_SZ;
    const float* Bg = Bw + (size_t)(blockIdx.x * 128) * D_SZ;

    const int lrow = tid >> 3;
    const int lc = tid & 7;

    auto issue_stage = [&](int it, int s) {
        const int k0 = it * 32;
        const uint32_t base = smb + (uint32_t)s * 2 * SSZ * 4;
#pragma unroll
        for (int i = 0; i < 4; i++) {
            const int row = lrow + 32 * i;
            const uint32_t off = (uint32_t)(row * SSTRIDE + lc * 4) * 4;
            cp16(base + off, Ag + (size_t)row * D_SZ + k0 + lc * 4);
            cp16(base + (uint32_t)SSZ * 4 + off, Bg + (size_t)row * D_SZ + k0 + lc * 4);
        }
        asm volatile("cp.async.commit_group;" ::: "memory");
    };

    float acc[4][4][4];
#pragma unroll
    for (int mi = 0; mi < 4; mi++)
#pragma unroll
        for (int ni = 0; ni < 4; ni++)
#pragma unroll
            for (int r = 0; r < 4; r++) acc[mi][ni][r] = 0.0f;

    issue_stage(0, 0);

    const int ar0 = warp_m * 64 + grp;
    const int bn0 = warp_n * 32 + grp;

    for (int it = 0; it < NCHUNK; ++it) {
        if (it + 1 < NCHUNK) issue_stage(it + 1, (it + 1) & 1);
        else asm volatile("cp.async.commit_group;" ::: "memory");
        asm volatile("cp.async.wait_group 1;" ::: "memory");
        __syncthreads();

        const uint32_t* Au = (const uint32_t*)(sm + (it & 1) * 2 * SSZ);
        const uint32_t* Bu = Au + SSZ;

#pragma unroll
        for (int ks = 0; ks < 4; ks++) {
            const int kc = ks * 8 + qid;
            uint32_t a[4][4], b[4][2];
#pragma unroll
            for (int mi = 0; mi < 4; mi++) {
                const int r = ar0 + mi * 16;
                a[mi][0] = Au[r * SSTRIDE + kc];
                a[mi][1] = Au[(r + 8) * SSTRIDE + kc];
                a[mi][2] = Au[r * SSTRIDE + kc + 4];
                a[mi][3] = Au[(r + 8) * SSTRIDE + kc + 4];
            }
#pragma unroll
            for (int ni = 0; ni < 4; ni++) {
                const int n = bn0 + ni * 8;
                b[ni][0] = Bu[n * SSTRIDE + kc];
                b[ni][1] = Bu[n * SSTRIDE + kc + 4];
            }
#pragma unroll
            for (int mi = 0; mi < 4; mi++)
#pragma unroll
                for (int ni = 0; ni < 4; ni++)
                    mma_tf32(acc[mi][ni][0], acc[mi][ni][1], acc[mi][ni][2], acc[mi][ni][3],
                             a[mi][0], a[mi][1], a[mi][2], a[mi][3],
                             b[ni][0], b[ni][1]);
        }
        __syncthreads();
    }

#pragma unroll
    for (int mi = 0; mi < 4; mi++) {
        const int row = blockIdx.y * 128 + warp_m * 64 + mi * 16 + grp;
#pragma unroll
        for (int ni = 0; ni < 4; ni++) {
            const int col = blockIdx.x * 128 + warp_n * 32 + ni * 8 + qid * 2;
            *(float2*)&C[(size_t)row * D_SZ + col] =
                make_float2(acc[mi][ni][0], acc[mi][ni][1]);
            *(float2*)&C[(size_t)(row + 8) * D_SZ + col] =
                make_float2(acc[mi][ni][2], acc[mi][ni][3]);
        }
    }
}

// ---------------------------------------------------------------------------
// RoPE + scale; writes tf32-rounded values (consumed by tensor-core attention)
// ---------------------------------------------------------------------------
__global__ void rope_kernel(float2* __restrict__ t,
                            const float* __restrict__ fcos,
                            const float* __restrict__ fsin,
                            float scale)
{
    int idx = blockIdx.x * blockDim.x + threadIdx.x;
    const int pairs = M_ROWS * D_SZ / 2;
    if (idx >= pairs) return;
    int i = idx & (HD_S / 2 - 1);
    int l = (idx / (D_SZ / 2)) % L_SZ;
    float c = fcos[l * (HD_S / 2) + i];
    float s = fsin[l * (HD_S / 2) + i];
    float2 v = t[idx];
    float2 o;
    o.x = to_tf32((v.x * c - v.y * s) * scale);
    o.y = to_tf32((v.x * s + v.y * c) * scale);
    t[idx] = o;
}

// ---------------------------------------------------------------------------
// Flash attention on tensor cores (tf32 mma.sync).
// Block: 256 thr (8 warps), Q tile 128 rows; warp w owns q rows 16w..16w+15.
// KV tiles of 64. Smem: Qs[128][132], Ks[64][132], Vs[64][136], Ps[128][68].
// ---------------------------------------------------------------------------
#define AQ_STR 132
#define AK_STR 132
#define AV_STR 136
#define AP_STR 68
#define ATT_SMEM_B ((128*AQ_STR + 64*AK_STR + 64*AV_STR + 128*AP_STR) * 4)

__global__ __launch_bounds__(256, 1) void attn_mma(const float* __restrict__ Q,
                                                   const float* __restrict__ Kg,
                                                   const float* __restrict__ Vg,
                                                   float* __restrict__ Og)
{
    extern __shared__ float sm[];
    float* Qs = sm;                       // [128][132]
    float* Ks = Qs + 128 * AQ_STR;        // [64][132]
    float* Vs = Ks + 64 * AK_STR;         // [64][136]
    float* Ps = Vs + 64 * AV_STR;         // [128][68]
    const uint32_t qsb = smem_u32(Qs), ksb = smem_u32(Ks), vsb = smem_u32(Vs);

    const int tid = threadIdx.x, lane = tid & 31, wid = tid >> 5;
    const int grp = lane >> 2, qid = lane & 3;
    const int bh = blockIdx.y, b = bh >> 5, h = bh & 31;
    const int q0 = blockIdx.x * 128;
    const size_t rowbase = (size_t)b * L_SZ;
    const size_t col0 = (size_t)h * HD_S;
    const int m0 = wid * 16;

    // Q tile: 128 rows x 32 16B-units, cp.async (drained by first wait_group 0)
    {
        const float* Qg = Q + (rowbase + q0) * D_SZ + col0;
#pragma unroll
        for (int i = 0; i < 16; i++) {
            const int u = tid + 256 * i, row = u >> 5, c = u & 31;
            cp16(qsb + (uint32_t)(row * AQ_STR + c * 4) * 4, Qg + (size_t)row * D_SZ + c * 4);
        }
        asm volatile("cp.async.commit_group;" ::: "memory");
    }

    float m_lo = -1e30f, m_hi = -1e30f, l_lo = 0.0f, l_hi = 0.0f;
    float o[16][4];
#pragma unroll
    for (int nb = 0; nb < 16; nb++)
#pragma unroll
        for (int r = 0; r < 4; r++) o[nb][r] = 0.0f;

    for (int kv = 0; kv < L_SZ; kv += 64) {
        const float* Kt = Kg + (rowbase + kv) * D_SZ + col0;
        const float* Vt = Vg + (rowbase + kv) * D_SZ + col0;
#pragma unroll
        for (int i = 0; i < 8; i++) {
            const int u = tid + 256 * i, row = u >> 5, c = u & 31;
            cp16(ksb + (uint32_t)(row * AK_STR + c * 4) * 4, Kt + (size_t)row * D_SZ + c * 4);
            cp16(vsb + (uint32_t)(row * AV_STR + c * 4) * 4, Vt + (size_t)row * D_SZ + c * 4);
        }
        asm volatile("cp.async.commit_group;" ::: "memory");
        asm volatile("cp.async.wait_group 0;" ::: "memory");
        __syncthreads();

        // ---- S = Q K^T : per-warp m16 x n64 ----
        float s[8][4];
#pragma unroll
        for (int nb = 0; nb < 8; nb++)
#pragma unroll
            for (int r = 0; r < 4; r++) s[nb][r] = 0.0f;

#pragma unroll 2
        for (int ks = 0; ks < 16; ks++) {
            const int kc = 8 * ks + qid;
            const uint32_t a0 = fu(Qs[(m0 + grp) * AQ_STR + kc]);
            const uint32_t a1 = fu(Qs[(m0 + grp + 8) * AQ_STR + kc]);
            const uint32_t a2 = fu(Qs[(m0 + grp) * AQ_STR + kc + 4]);
            const uint32_t a3 = fu(Qs[(m0 + grp + 8) * AQ_STR + kc + 4]);
#pragma unroll
            for (int nb = 0; nb < 8; nb++) {
                const uint32_t b0 = fu(Ks[(8 * nb + grp) * AK_STR + kc]);
                const uint32_t b1 = fu(Ks[(8 * nb + grp) * AK_STR + kc + 4]);
                mma_tf32(s[nb][0], s[nb][1], s[nb][2], s[nb][3], a0, a1, a2, a3, b0, b1);
            }
        }

        // ---- online softmax on fragments (rows grp / grp+8) ----
        float tl = -1e30f, th = -1e30f;
#pragma unroll
        for (int nb = 0; nb < 8; nb++) {
            tl = fmaxf(tl, fmaxf(s[nb][0], s[nb][1]));
            th = fmaxf(th, fmaxf(s[nb][2], s[nb][3]));
        }
        tl = fmaxf(tl, __shfl_xor_sync(0xffffffffu, tl, 1));
        tl = fmaxf(tl, __shfl_xor_sync(0xffffffffu, tl, 2));
        th = fmaxf(th, __shfl_xor_sync(0xffffffffu, th, 1));
        th = fmaxf(th, __shfl_xor_sync(0xffffffffu, th, 2));
        const float mnl = fmaxf(m_lo, tl), mnh = fmaxf(m_hi, th);
        const float cl = __expf(m_lo - mnl), ch = __expf(m_hi - mnh);
        float rl = 0.0f, rh = 0.0f;
#pragma unroll
        for (int nb = 0; nb < 8; nb++) {
            s[nb][0] = to_tf32(__expf(s[nb][0] - mnl));
            s[nb][1] = to_tf32(__expf(s[nb][1] - mnl));
            s[nb][2] = to_tf32(__expf(s[nb][2] - mnh));
            s[nb][3] = to_tf32(__expf(s[nb][3] - mnh));
            rl += s[nb][0] + s[nb][1];
            rh += s[nb][2] + s[nb][3];
        }
        rl += __shfl_xor_sync(0xffffffffu, rl, 1);
        rl += __shfl_xor_sync(0xffffffffu, rl, 2);
        rh += __shfl_xor_sync(0xffffffffu, rh, 1);
        rh += __shfl_xor_sync(0xffffffffu, rh, 2);
        l_lo = l_lo * cl + rl; m_lo = mnl;
        l_hi = l_hi * ch + rh; m_hi = mnh;
#pragma unroll
        for (int nb = 0; nb < 16; nb++) {
            o[nb][0] *= cl; o[nb][1] *= cl;
            o[nb][2] *= ch; o[nb][3] *= ch;
        }

        // store P (warp-private rows), accum layout -> row-major smem
#pragma unroll
        for (int nb = 0; nb < 8; nb++) {
            *(float2*)&Ps[(m0 + grp) * AP_STR + 8 * nb + 2 * qid] =
                make_float2(s[nb][0], s[nb][1]);
            *(float2*)&Ps[(m0 + grp + 8) * AP_STR + 8 * nb + 2 * qid] =
                make_float2(s[nb][2], s[nb][3]);
        }
        __syncwarp();

        // ---- O += P V : m16 x n128, K=64 ----
#pragma unroll 2
        for (int ks = 0; ks < 8; ks++) {
            const int kc = 8 * ks + qid;
            const uint32_t a0 = fu(Ps[(m0 + grp) * AP_STR + kc]);
            const uint32_t a1 = fu(Ps[(m0 + grp + 8) * AP_STR + kc]);
            const uint32_t a2 = fu(Ps[(m0 + grp) * AP_STR + kc + 4]);
            const uint32_t a3 = fu(Ps[(m0 + grp + 8) * AP_STR + kc + 4]);
#pragma unroll
            for (int nb = 0; nb < 16; nb++) {
                const uint32_t b0 = fu(Vs[(8 * ks + qid) * AV_STR + 8 * nb + grp]);
                const uint32_t b1 = fu(Vs[(8 * ks + qid + 4) * AV_STR + 8 * nb + grp]);
                mma_tf32(o[nb][0], o[nb][1], o[nb][2], o[nb][3], a0, a1, a2, a3, b0, b1);
            }
        }
        __syncthreads();   // protect Ks/Vs for next iteration
    }

    // epilogue: normalize, tf32-round (next GEMM consumes), write
    const float il = 1.0f / l_lo, ih = 1.0f / l_hi;
    const size_t row_lo = rowbase + q0 + m0 + grp;
    const size_t row_hi = row_lo + 8;
#pragma unroll
    for (int nb = 0; nb < 16; nb++) {
        const size_t col = col0 + 8 * nb + 2 * qid;
        *(float2*)&Og[row_lo * D_SZ + col] =
            make_float2(to_tf32(o[nb][0] * il), to_tf32(o[nb][1] * il));
        *(float2*)&Og[row_hi * D_SZ + col] =
            make_float2(to_tf32(o[nb][2] * ih), to_tf32(o[nb][3] * ih));
    }
}

// ---------------------------------------------------------------------------
// Launch.  Order matters for ncu (-s 5 -c 1): launch #5 must be gemm_tf32.
// ---------------------------------------------------------------------------
extern "C" void kernel_launch(void* const* d_in, const int* in_sizes, int n_in,
                              void* d_out, int out_size)
{
    (void)in_sizes; (void)n_in; (void)out_size;
    const float* x    = (const float*)d_in[0];
    const float* fcos = (const float*)d_in[1];
    const float* fsin = (const float*)d_in[2];
    const float* Wq   = (const float*)d_in[3];
    const float* Wk   = (const float*)d_in[4];
    const float* Wv   = (const float*)d_in[5];
    const float* Wo   = (const float*)d_in[6];
    float* out = (float*)d_out;

    float *Qb, *Kb, *Vb, *Ab, *Xc, *Wqc, *Wkc, *Wvc, *Woc;
    cudaGetSymbolAddress((void**)&Qb, g_Q);
    cudaGetSymbolAddress((void**)&Kb, g_K);
    cudaGetSymbolAddress((void**)&Vb, g_V);
    cudaGetSymbolAddress((void**)&Ab, g_A);
    cudaGetSymbolAddress((void**)&Xc, g_Xc);
    cudaGetSymbolAddress((void**)&Wqc, g_Wqc);
    cudaGetSymbolAddress((void**)&Wkc, g_Wkc);
    cudaGetSymbolAddress((void**)&Wvc, g_Wvc);
    cudaGetSymbolAddress((void**)&Woc, g_Woc);

    const int n4 = M_ROWS * D_SZ / 4;
    const int CVB = 256, CVG = (n4 + CVB - 1) / CVB;

    const size_t GEMM_SMEM = (size_t)2 * 2 * SSZ * sizeof(float);   // 73728 B
    cudaFuncSetAttribute(gemm_tf32, cudaFuncAttributeMaxDynamicSharedMemorySize,
                         (int)GEMM_SMEM);
    cudaFuncSetAttribute(attn_mma, cudaFuncAttributeMaxDynamicSharedMemorySize,
                         ATT_SMEM_B);

    dim3 gg(D_SZ / 128, M_ROWS / 128);

    // 0-4: tf32 rounding passes (all weights + x up front)
    cvt_tf32_kernel<<<CVG, CVB>>>((const float4*)x,  (float4*)Xc,  n4);
    cvt_tf32_kernel<<<CVG, CVB>>>((const float4*)Wq, (float4*)Wqc, n4);
    cvt_tf32_kernel<<<CVG, CVB>>>((const float4*)Wk, (float4*)Wkc, n4);
    cvt_tf32_kernel<<<CVG, CVB>>>((const float4*)Wv, (float4*)Wvc, n4);
    cvt_tf32_kernel<<<CVG, CVB>>>((const float4*)Wo, (float4*)Woc, n4);

    // 5-7: projections (launch #5 = gemm -> ncu profiles it)
    gemm_tf32<<<gg, 256, GEMM_SMEM>>>(Xc, Wqc, Qb);
    gemm_tf32<<<gg, 256, GEMM_SMEM>>>(Xc, Wkc, Kb);
    gemm_tf32<<<gg, 256, GEMM_SMEM>>>(Xc, Wvc, Vb);

    // 8-10: rope (writes tf32-rounded), V rounding in-place
    const int pairs = M_ROWS * D_SZ / 2;
    const float qscale = 0.08838834764831845f;  // 1/sqrt(128)
    rope_kernel<<<(pairs + 255) / 256, 256>>>((float2*)Qb, fcos, fsin, qscale);
    rope_kernel<<<(pairs + 255) / 256, 256>>>((float2*)Kb, fcos, fsin, 1.0f);
    cvt_tf32_kernel<<<CVG, CVB>>>((const float4*)Vb, (float4*)Vb, n4);

    // 11: attention (tensor cores); writes tf32-rounded A
    attn_mma<<<dim3(L_SZ / 128, B_SZ * H_N), 256, ATT_SMEM_B>>>(Qb, Kb, Vb, Ab);

    // 12: output projection
    gemm_tf32<<<gg, 256, GEMM_SMEM>>>(Ab, Woc, out);
}

// round 7
// speedup vs baseline: 3.7973x; 1.0640x over previous
#include <cuda_runtime.h>
#include <cstdint>
#include <math.h>

// Problem constants
#define B_SZ 2
#define L_SZ 2048
#define D_SZ 4096
#define H_N  32
#define HD_S 128
#define M_ROWS (B_SZ * L_SZ)   // 4096

// ---------------------------------------------------------------------------
// Scratch (device globals: allocation-free per harness rules)
// ---------------------------------------------------------------------------
__device__ __align__(256) float g_Q[(size_t)M_ROWS * D_SZ];
__device__ __align__(256) float g_K[(size_t)M_ROWS * D_SZ];
__device__ __align__(256) float g_V[(size_t)M_ROWS * D_SZ];
__device__ __align__(256) float g_A[(size_t)M_ROWS * D_SZ];
__device__ __align__(256) float g_Xc[(size_t)M_ROWS * D_SZ];
__device__ __align__(256) float g_Wqc[(size_t)D_SZ * D_SZ];
__device__ __align__(256) float g_Wkc[(size_t)D_SZ * D_SZ];
__device__ __align__(256) float g_Wvc[(size_t)D_SZ * D_SZ];
__device__ __align__(256) float g_Woc[(size_t)D_SZ * D_SZ];

// ---------------------------------------------------------------------------
// Helpers
// ---------------------------------------------------------------------------
__device__ __forceinline__ uint32_t smem_u32(const void* p) {
    uint32_t a;
    asm("{ .reg .u64 t; cvta.to.shared.u64 t, %1; cvt.u32.u64 %0, t; }"
        : "=r"(a) : "l"(p));
    return a;
}
__device__ __forceinline__ void cp16(uint32_t saddr, const void* gaddr) {
    asm volatile("cp.async.cg.shared.global [%0], [%1], 16;" :: "r"(saddr), "l"(gaddr));
}
__device__ __forceinline__ void ldsm_x4(uint32_t* r, uint32_t addr) {
    asm volatile("ldmatrix.sync.aligned.m8n8.x4.shared.b16 {%0,%1,%2,%3}, [%4];"
                 : "=r"(r[0]), "=r"(r[1]), "=r"(r[2]), "=r"(r[3]) : "r"(addr));
}
__device__ __forceinline__ void mma_tf32(float& c0, float& c1, float& c2, float& c3,
                                         uint32_t a0, uint32_t a1, uint32_t a2, uint32_t a3,
                                         uint32_t b0, uint32_t b1) {
    asm volatile(
        "mma.sync.aligned.m16n8k8.row.col.f32.tf32.tf32.f32 "
        "{%0,%1,%2,%3}, {%4,%5,%6,%7}, {%8,%9}, {%0,%1,%2,%3};"
        : "+f"(c0), "+f"(c1), "+f"(c2), "+f"(c3)
        : "r"(a0), "r"(a1), "r"(a2), "r"(a3), "r"(b0), "r"(b1));
}
__device__ __forceinline__ float to_tf32(float f) {
    uint32_t o;
    asm("cvt.rna.tf32.f32 %0, %1;" : "=r"(o) : "f"(f));
    return __uint_as_float(o);
}
__device__ __forceinline__ uint32_t fu(float f) { return __float_as_uint(f); }

__global__ void cvt_tf32_kernel(const float4* __restrict__ in, float4* __restrict__ out, int n4) {
    int i = blockIdx.x * blockDim.x + threadIdx.x;
    if (i >= n4) return;
    float4 v = in[i];
    v.x = to_tf32(v.x); v.y = to_tf32(v.y); v.z = to_tf32(v.z); v.w = to_tf32(v.w);
    out[i] = v;
}

// ---------------------------------------------------------------------------
// tf32 GEMM via mma.sync + ldmatrix: C = A * Bw^T (row-major, K contiguous)
// 128x128 CTA tile, BK=32, 8 warps (2x4), warp tile 64x32, 2-stage cp.async.
// Fragment loads via ldmatrix.x4 (24 per warp-chunk instead of 96 LDS).
// ---------------------------------------------------------------------------
#define SSTRIDE 36
#define SSZ (128 * SSTRIDE)
#define NCHUNK (D_SZ / 32)

__global__ __launch_bounds__(256, 2) void gemm_tf32(const float* __restrict__ A,
                                                    const float* __restrict__ Bw,
                                                    float* __restrict__ C)
{
    extern __shared__ float sm[];
    const uint32_t smb = smem_u32(sm);
    const int tid = threadIdx.x;
    const int lane = tid & 31, wid = tid >> 5;
    const int warp_m = wid >> 2, warp_n = wid & 3;
    const int grp = lane >> 2, qid = lane & 3;
    const int lm = lane >> 3, lr = lane & 7;     // ldmatrix: matrix id, row-in-matrix

    const float* Ag = A + (size_t)(blockIdx.y * 128) * D_SZ;
    const float* Bg = Bw + (size_t)(blockIdx.x * 128) * D_SZ;

    const int lrow = tid >> 3;
    const int lc = tid & 7;

    auto issue_stage = [&](int it, int s) {
        const int k0 = it * 32;
        const uint32_t base = smb + (uint32_t)s * 2 * SSZ * 4;
#pragma unroll
        for (int i = 0; i < 4; i++) {
            const int row = lrow + 32 * i;
            const uint32_t off = (uint32_t)(row * SSTRIDE + lc * 4) * 4;
            cp16(base + off, Ag + (size_t)row * D_SZ + k0 + lc * 4);
            cp16(base + (uint32_t)SSZ * 4 + off, Bg + (size_t)row * D_SZ + k0 + lc * 4);
        }
        asm volatile("cp.async.commit_group;" ::: "memory");
    };

    float acc[4][4][4];
#pragma unroll
    for (int mi = 0; mi < 4; mi++)
#pragma unroll
        for (int ni = 0; ni < 4; ni++)
#pragma unroll
            for (int r = 0; r < 4; r++) acc[mi][ni][r] = 0.0f;

    issue_stage(0, 0);

    // ldmatrix per-lane base offsets (floats), relative to stage base:
    //  A frag (mi,ks): rows warp_m*64+mi*16 + lr + (lm&1)*8, cols ks*8 + (lm>>1)*4
    //  B frag (ni,j):  rows warp_n*32+ni*8 + lr,             cols j*16 + lm*4
    const uint32_t aoff0 = (uint32_t)((warp_m * 64 + lr + (lm & 1) * 8) * SSTRIDE
                                      + (lm >> 1) * 4) * 4;
    const uint32_t boff0 = (uint32_t)((warp_n * 32 + lr) * SSTRIDE + lm * 4) * 4;

    for (int it = 0; it < NCHUNK; ++it) {
        if (it + 1 < NCHUNK) issue_stage(it + 1, (it + 1) & 1);
        else asm volatile("cp.async.commit_group;" ::: "memory");
        asm volatile("cp.async.wait_group 1;" ::: "memory");
        __syncthreads();

        const uint32_t aBase = smb + (uint32_t)(it & 1) * 2 * SSZ * 4 + aoff0;
        const uint32_t bBase = smb + (uint32_t)(it & 1) * 2 * SSZ * 4
                               + (uint32_t)SSZ * 4 + boff0;

#pragma unroll
        for (int j = 0; j < 2; j++) {           // ks pairs (2j, 2j+1)
            uint32_t bb[4][4];
#pragma unroll
            for (int ni = 0; ni < 4; ni++)
                ldsm_x4(bb[ni], bBase + (uint32_t)(ni * 8 * SSTRIDE + j * 16) * 4);
#pragma unroll
            for (int s = 0; s < 2; s++) {       // ks = 2j+s
                const int ks = 2 * j + s;
                uint32_t aa[4][4];
#pragma unroll
                for (int mi = 0; mi < 4; mi++)
                    ldsm_x4(aa[mi], aBase + (uint32_t)(mi * 16 * SSTRIDE + ks * 8) * 4);
#pragma unroll
                for (int mi = 0; mi < 4; mi++)
#pragma unroll
                    for (int ni = 0; ni < 4; ni++)
                        mma_tf32(acc[mi][ni][0], acc[mi][ni][1],
                                 acc[mi][ni][2], acc[mi][ni][3],
                                 aa[mi][0], aa[mi][1], aa[mi][2], aa[mi][3],
                                 bb[ni][2 * s], bb[ni][2 * s + 1]);
            }
        }
        __syncthreads();
    }

#pragma unroll
    for (int mi = 0; mi < 4; mi++) {
        const int row = blockIdx.y * 128 + warp_m * 64 + mi * 16 + grp;
#pragma unroll
        for (int ni = 0; ni < 4; ni++) {
            const int col = blockIdx.x * 128 + warp_n * 32 + ni * 8 + qid * 2;
            *(float2*)&C[(size_t)row * D_SZ + col] =
                make_float2(acc[mi][ni][0], acc[mi][ni][1]);
            *(float2*)&C[(size_t)(row + 8) * D_SZ + col] =
                make_float2(acc[mi][ni][2], acc[mi][ni][3]);
        }
    }
}

// ---------------------------------------------------------------------------
// RoPE + scale; writes tf32-rounded values
// ---------------------------------------------------------------------------
__global__ void rope_kernel(float2* __restrict__ t,
                            const float* __restrict__ fcos,
                            const float* __restrict__ fsin,
                            float scale)
{
    int idx = blockIdx.x * blockDim.x + threadIdx.x;
    const int pairs = M_ROWS * D_SZ / 2;
    if (idx >= pairs) return;
    int i = idx & (HD_S / 2 - 1);
    int l = (idx / (D_SZ / 2)) % L_SZ;
    float c = fcos[l * (HD_S / 2) + i];
    float s = fsin[l * (HD_S / 2) + i];
    float2 v = t[idx];
    float2 o;
    o.x = to_tf32((v.x * c - v.y * s) * scale);
    o.y = to_tf32((v.x * s + v.y * c) * scale);
    t[idx] = o;
}

// ---------------------------------------------------------------------------
// Flash attention on tensor cores (tf32 mma.sync) — unchanged from R6
// ---------------------------------------------------------------------------
#define AQ_STR 132
#define AK_STR 132
#define AV_STR 136
#define AP_STR 68
#define ATT_SMEM_B ((128*AQ_STR + 64*AK_STR + 64*AV_STR + 128*AP_STR) * 4)

__global__ __launch_bounds__(256, 1) void attn_mma(const float* __restrict__ Q,
                                                   const float* __restrict__ Kg,
                                                   const float* __restrict__ Vg,
                                                   float* __restrict__ Og)
{
    extern __shared__ float sm[];
    float* Qs = sm;                       // [128][132]
    float* Ks = Qs + 128 * AQ_STR;        // [64][132]
    float* Vs = Ks + 64 * AK_STR;         // [64][136]
    float* Ps = Vs + 64 * AV_STR;         // [128][68]
    const uint32_t qsb = smem_u32(Qs), ksb = smem_u32(Ks), vsb = smem_u32(Vs);

    const int tid = threadIdx.x, lane = tid & 31, wid = tid >> 5;
    const int grp = lane >> 2, qid = lane & 3;
    const int bh = blockIdx.y, b = bh >> 5, h = bh & 31;
    const int q0 = blockIdx.x * 128;
    const size_t rowbase = (size_t)b * L_SZ;
    const size_t col0 = (size_t)h * HD_S;
    const int m0 = wid * 16;

    {
        const float* Qg = Q + (rowbase + q0) * D_SZ + col0;
#pragma unroll
        for (int i = 0; i < 16; i++) {
            const int u = tid + 256 * i, row = u >> 5, c = u & 31;
            cp16(qsb + (uint32_t)(row * AQ_STR + c * 4) * 4, Qg + (size_t)row * D_SZ + c * 4);
        }
        asm volatile("cp.async.commit_group;" ::: "memory");
    }

    float m_lo = -1e30f, m_hi = -1e30f, l_lo = 0.0f, l_hi = 0.0f;
    float o[16][4];
#pragma unroll
    for (int nb = 0; nb < 16; nb++)
#pragma unroll
        for (int r = 0; r < 4; r++) o[nb][r] = 0.0f;

    for (int kv = 0; kv < L_SZ; kv += 64) {
        const float* Kt = Kg + (rowbase + kv) * D_SZ + col0;
        const float* Vt = Vg + (rowbase + kv) * D_SZ + col0;
#pragma unroll
        for (int i = 0; i < 8; i++) {
            const int u = tid + 256 * i, row = u >> 5, c = u & 31;
            cp16(ksb + (uint32_t)(row * AK_STR + c * 4) * 4, Kt + (size_t)row * D_SZ + c * 4);
            cp16(vsb + (uint32_t)(row * AV_STR + c * 4) * 4, Vt + (size_t)row * D_SZ + c * 4);
        }
        asm volatile("cp.async.commit_group;" ::: "memory");
        asm volatile("cp.async.wait_group 0;" ::: "memory");
        __syncthreads();

        float s[8][4];
#pragma unroll
        for (int nb = 0; nb < 8; nb++)
#pragma unroll
            for (int r = 0; r < 4; r++) s[nb][r] = 0.0f;

#pragma unroll 2
        for (int ks = 0; ks < 16; ks++) {
            const int kc = 8 * ks + qid;
            const uint32_t a0 = fu(Qs[(m0 + grp) * AQ_STR + kc]);
            const uint32_t a1 = fu(Qs[(m0 + grp + 8) * AQ_STR + kc]);
            const uint32_t a2 = fu(Qs[(m0 + grp) * AQ_STR + kc + 4]);
            const uint32_t a3 = fu(Qs[(m0 + grp + 8) * AQ_STR + kc + 4]);
#pragma unroll
            for (int nb = 0; nb < 8; nb++) {
                const uint32_t b0 = fu(Ks[(8 * nb + grp) * AK_STR + kc]);
                const uint32_t b1 = fu(Ks[(8 * nb + grp) * AK_STR + kc + 4]);
                mma_tf32(s[nb][0], s[nb][1], s[nb][2], s[nb][3], a0, a1, a2, a3, b0, b1);
            }
        }

        float tl = -1e30f, th = -1e30f;
#pragma unroll
        for (int nb = 0; nb < 8; nb++) {
            tl = fmaxf(tl, fmaxf(s[nb][0], s[nb][1]));
            th = fmaxf(th, fmaxf(s[nb][2], s[nb][3]));
        }
        tl = fmaxf(tl, __shfl_xor_sync(0xffffffffu, tl, 1));
        tl = fmaxf(tl, __shfl_xor_sync(0xffffffffu, tl, 2));
        th = fmaxf(th, __shfl_xor_sync(0xffffffffu, th, 1));
        th = fmaxf(th, __shfl_xor_sync(0xffffffffu, th, 2));
        const float mnl = fmaxf(m_lo, tl), mnh = fmaxf(m_hi, th);
        const float cl = __expf(m_lo - mnl), ch = __expf(m_hi - mnh);
        float rl = 0.0f, rh = 0.0f;
#pragma unroll
        for (int nb = 0; nb < 8; nb++) {
            s[nb][0] = to_tf32(__expf(s[nb][0] - mnl));
            s[nb][1] = to_tf32(__expf(s[nb][1] - mnl));
            s[nb][2] = to_tf32(__expf(s[nb][2] - mnh));
            s[nb][3] = to_tf32(__expf(s[nb][3] - mnh));
            rl += s[nb][0] + s[nb][1];
            rh += s[nb][2] + s[nb][3];
        }
        rl += __shfl_xor_sync(0xffffffffu, rl, 1);
        rl += __shfl_xor_sync(0xffffffffu, rl, 2);
        rh += __shfl_xor_sync(0xffffffffu, rh, 1);
        rh += __shfl_xor_sync(0xffffffffu, rh, 2);
        l_lo = l_lo * cl + rl; m_lo = mnl;
        l_hi = l_hi * ch + rh; m_hi = mnh;
#pragma unroll
        for (int nb = 0; nb < 16; nb++) {
            o[nb][0] *= cl; o[nb][1] *= cl;
            o[nb][2] *= ch; o[nb][3] *= ch;
        }

#pragma unroll
        for (int nb = 0; nb < 8; nb++) {
            *(float2*)&Ps[(m0 + grp) * AP_STR + 8 * nb + 2 * qid] =
                make_float2(s[nb][0], s[nb][1]);
            *(float2*)&Ps[(m0 + grp + 8) * AP_STR + 8 * nb + 2 * qid] =
                make_float2(s[nb][2], s[nb][3]);
        }
        __syncwarp();

#pragma unroll 2
        for (int ks = 0; ks < 8; ks++) {
            const int kc = 8 * ks + qid;
            const uint32_t a0 = fu(Ps[(m0 + grp) * AP_STR + kc]);
            const uint32_t a1 = fu(Ps[(m0 + grp + 8) * AP_STR + kc]);
            const uint32_t a2 = fu(Ps[(m0 + grp) * AP_STR + kc + 4]);
            const uint32_t a3 = fu(Ps[(m0 + grp + 8) * AP_STR + kc + 4]);
#pragma unroll
            for (int nb = 0; nb < 16; nb++) {
                const uint32_t b0 = fu(Vs[(8 * ks + qid) * AV_STR + 8 * nb + grp]);
                const uint32_t b1 = fu(Vs[(8 * ks + qid + 4) * AV_STR + 8 * nb + grp]);
                mma_tf32(o[nb][0], o[nb][1], o[nb][2], o[nb][3], a0, a1, a2, a3, b0, b1);
            }
        }
        __syncthreads();
    }

    const float il = 1.0f / l_lo, ih = 1.0f / l_hi;
    const size_t row_lo = rowbase + q0 + m0 + grp;
    const size_t row_hi = row_lo + 8;
#pragma unroll
    for (int nb = 0; nb < 16; nb++) {
        const size_t col = col0 + 8 * nb + 2 * qid;
        *(float2*)&Og[row_lo * D_SZ + col] =
            make_float2(to_tf32(o[nb][0] * il), to_tf32(o[nb][1] * il));
        *(float2*)&Og[row_hi * D_SZ + col] =
            make_float2(to_tf32(o[nb][2] * ih), to_tf32(o[nb][3] * ih));
    }
}

// ---------------------------------------------------------------------------
// Launch. gemm launches at slots 4,5,6 so ncu (-s 5 +/- offset) hits a gemm.
// ---------------------------------------------------------------------------
extern "C" void kernel_launch(void* const* d_in, const int* in_sizes, int n_in,
                              void* d_out, int out_size)
{
    (void)in_sizes; (void)n_in; (void)out_size;
    const float* x    = (const float*)d_in[0];
    const float* fcos = (const float*)d_in[1];
    const float* fsin = (const float*)d_in[2];
    const float* Wq   = (const float*)d_in[3];
    const float* Wk   = (const float*)d_in[4];
    const float* Wv   = (const float*)d_in[5];
    const float* Wo   = (const float*)d_in[6];
    float* out = (float*)d_out;

    float *Qb, *Kb, *Vb, *Ab, *Xc, *Wqc, *Wkc, *Wvc, *Woc;
    cudaGetSymbolAddress((void**)&Qb, g_Q);
    cudaGetSymbolAddress((void**)&Kb, g_K);
    cudaGetSymbolAddress((void**)&Vb, g_V);
    cudaGetSymbolAddress((void**)&Ab, g_A);
    cudaGetSymbolAddress((void**)&Xc, g_Xc);
    cudaGetSymbolAddress((void**)&Wqc, g_Wqc);
    cudaGetSymbolAddress((void**)&Wkc, g_Wkc);
    cudaGetSymbolAddress((void**)&Wvc, g_Wvc);
    cudaGetSymbolAddress((void**)&Woc, g_Woc);

    const int n4 = M_ROWS * D_SZ / 4;
    const int CVB = 256, CVG = (n4 + CVB - 1) / CVB;

    const size_t GEMM_SMEM = (size_t)2 * 2 * SSZ * sizeof(float);   // 73728 B
    cudaFuncSetAttribute(gemm_tf32, cudaFuncAttributeMaxDynamicSharedMemorySize,
                         (int)GEMM_SMEM);
    cudaFuncSetAttribute(attn_mma, cudaFuncAttributeMaxDynamicSharedMemorySize,
                         ATT_SMEM_B);

    dim3 gg(D_SZ / 128, M_ROWS / 128);

    // 0-3: tf32 rounding (x + QKV weights)
    cvt_tf32_kernel<<<CVG, CVB>>>((const float4*)x,  (float4*)Xc,  n4);
    cvt_tf32_kernel<<<CVG, CVB>>>((const float4*)Wq, (float4*)Wqc, n4);
    cvt_tf32_kernel<<<CVG, CVB>>>((const float4*)Wk, (float4*)Wkc, n4);
    cvt_tf32_kernel<<<CVG, CVB>>>((const float4*)Wv, (float4*)Wvc, n4);

    // 4-6: projections (ncu -s 5 lands on one of these)
    gemm_tf32<<<gg, 256, GEMM_SMEM>>>(Xc, Wqc, Qb);
    gemm_tf32<<<gg, 256, GEMM_SMEM>>>(Xc, Wkc, Kb);
    gemm_tf32<<<gg, 256, GEMM_SMEM>>>(Xc, Wvc, Vb);

    // 7: Wo rounding (needed only before final gemm)
    cvt_tf32_kernel<<<CVG, CVB>>>((const float4*)Wo, (float4*)Woc, n4);

    // 8-10: rope (tf32-rounded out) + V rounding
    const int pairs = M_ROWS * D_SZ / 2;
    const float qscale = 0.08838834764831845f;  // 1/sqrt(128)
    rope_kernel<<<(pairs + 255) / 256, 256>>>((float2*)Qb, fcos, fsin, qscale);
    rope_kernel<<<(pairs + 255) / 256, 256>>>((float2*)Kb, fcos, fsin, 1.0f);
    cvt_tf32_kernel<<<CVG, CVB>>>((const float4*)Vb, (float4*)Vb, n4);

    // 11: attention
    attn_mma<<<dim3(L_SZ / 128, B_SZ * H_N), 256, ATT_SMEM_B>>>(Qb, Kb, Vb, Ab);

    // 12: output projection
    gemm_tf32<<<gg, 256, GEMM_SMEM>>>(Ab, Woc, out);
}

// round 8
// speedup vs baseline: 7.4928x; 1.9732x over previous
#include <cuda_runtime.h>
#include <cuda_fp16.h>
#include <cstdint>
#include <math.h>

// Problem constants
#define B_SZ 2
#define L_SZ 2048
#define D_SZ 4096
#define H_N  32
#define HD_S 128
#define M_ROWS (B_SZ * L_SZ)   // 4096
#define NELEM ((size_t)M_ROWS * D_SZ)

// ---------------------------------------------------------------------------
// Scratch (device globals; fp16 intermediates)
// ---------------------------------------------------------------------------
__device__ __align__(256) __half g_Q[NELEM];
__device__ __align__(256) __half g_K[NELEM];
__device__ __align__(256) __half g_V[NELEM];
__device__ __align__(256) __half g_A[NELEM];
__device__ __align__(256) __half g_Xc[NELEM];
__device__ __align__(256) __half g_Wqc[NELEM];
__device__ __align__(256) __half g_Wkc[NELEM];
__device__ __align__(256) __half g_Wvc[NELEM];
__device__ __align__(256) __half g_Woc[NELEM];

// ---------------------------------------------------------------------------
// Helpers
// ---------------------------------------------------------------------------
__device__ __forceinline__ uint32_t smem_u32(const void* p) {
    uint32_t a;
    asm("{ .reg .u64 t; cvta.to.shared.u64 t, %1; cvt.u32.u64 %0, t; }"
        : "=r"(a) : "l"(p));
    return a;
}
__device__ __forceinline__ void cp16(uint32_t saddr, const void* gaddr) {
    asm volatile("cp.async.cg.shared.global [%0], [%1], 16;" :: "r"(saddr), "l"(gaddr));
}
__device__ __forceinline__ void ldsm_x4(uint32_t* r, uint32_t addr) {
    asm volatile("ldmatrix.sync.aligned.m8n8.x4.shared.b16 {%0,%1,%2,%3}, [%4];"
                 : "=r"(r[0]), "=r"(r[1]), "=r"(r[2]), "=r"(r[3]) : "r"(addr));
}
__device__ __forceinline__ void ldsm_x4t(uint32_t* r, uint32_t addr) {
    asm volatile("ldmatrix.sync.aligned.m8n8.x4.trans.shared.b16 {%0,%1,%2,%3}, [%4];"
                 : "=r"(r[0]), "=r"(r[1]), "=r"(r[2]), "=r"(r[3]) : "r"(addr));
}
__device__ __forceinline__ void mma_f16(float& c0, float& c1, float& c2, float& c3,
                                        uint32_t a0, uint32_t a1, uint32_t a2, uint32_t a3,
                                        uint32_t b0, uint32_t b1) {
    asm volatile(
        "mma.sync.aligned.m16n8k16.row.col.f32.f16.f16.f32 "
        "{%0,%1,%2,%3}, {%4,%5,%6,%7}, {%8,%9}, {%0,%1,%2,%3};"
        : "+f"(c0), "+f"(c1), "+f"(c2), "+f"(c3)
        : "r"(a0), "r"(a1), "r"(a2), "r"(a3), "r"(b0), "r"(b1));
}
__device__ __forceinline__ uint32_t pack2h(float a, float b) {
    __half2 h = __floats2half2_rn(a, b);
    return *(uint32_t*)&h;
}

// ---------------------------------------------------------------------------
// Fused fp32->fp16 (RN) conversion of x + 4 weights (1 launch)
// ---------------------------------------------------------------------------
__global__ void cvt_f16_fused(const float* __restrict__ x,  const float* __restrict__ wq,
                              const float* __restrict__ wk, const float* __restrict__ wv,
                              const float* __restrict__ wo,
                              __half* xc, __half* wqc, __half* wkc, __half* wvc, __half* woc)
{
    const float* src; __half* dst;
    switch (blockIdx.y) {
        case 0: src = x;  dst = xc;  break;
        case 1: src = wq; dst = wqc; break;
        case 2: src = wk; dst = wkc; break;
        case 3: src = wv; dst = wvc; break;
        default: src = wo; dst = woc; break;
    }
    size_t i = (size_t)blockIdx.x * blockDim.x + threadIdx.x;   // 8-elt groups
    if (i >= NELEM / 8) return;
    float4 v0 = ((const float4*)src)[2 * i];
    float4 v1 = ((const float4*)src)[2 * i + 1];
    uint4 o;
    o.x = pack2h(v0.x, v0.y); o.y = pack2h(v0.z, v0.w);
    o.z = pack2h(v1.x, v1.y); o.w = pack2h(v1.z, v1.w);
    ((uint4*)dst)[i] = o;
}

// ---------------------------------------------------------------------------
// fp16 GEMM via mma.sync.m16n8k16 + ldmatrix: C = A * Bw^T (row-major, K contig)
// 128x128 CTA tile, BK=64, 8 warps (2x4), warp tile 64x32, 2-stage cp.async.
// Smem rows stride 72 halves (144B): bank start 4r mod 32 -> conflict-free ldsm.
// ---------------------------------------------------------------------------
#define GSTR 72
#define GTILE_B (128 * GSTR * 2)     // 18432 B per operand per stage
#define GNCHUNK (D_SZ / 64)          // 64

template <bool HOUT>
__global__ __launch_bounds__(256, 2) void gemm_f16(const __half* __restrict__ A,
                                                   const __half* __restrict__ Bw,
                                                   void* __restrict__ Cv)
{
    extern __shared__ __half smh[];
    const uint32_t smb = smem_u32(smh);
    const int tid = threadIdx.x;
    const int lane = tid & 31, wid = tid >> 5;
    const int warp_m = wid >> 2, warp_n = wid & 3;
    const int grp = lane >> 2, qid = lane & 3;
    const int lm = lane >> 3, lr = lane & 7;

    const __half* Ag = A + (size_t)(blockIdx.y * 128) * D_SZ;
    const __half* Bg = Bw + (size_t)(blockIdx.x * 128) * D_SZ;

    auto issue_stage = [&](int it, int s) {
        const int k0 = it * 64;
        const uint32_t base = smb + (uint32_t)s * 2 * GTILE_B;
#pragma unroll
        for (int i = 0; i < 8; i++) {
            const int u = tid + 256 * i;
            const int v = u & 1023;
            const int row = v >> 3, c = v & 7;
            const uint32_t so = (uint32_t)(row * GSTR + c * 8) * 2;
            if (u < 1024)
                cp16(base + so, Ag + (size_t)row * D_SZ + k0 + c * 8);
            else
                cp16(base + GTILE_B + so, Bg + (size_t)row * D_SZ + k0 + c * 8);
        }
        asm volatile("cp.async.commit_group;" ::: "memory");
    };

    float acc[4][4][4];
#pragma unroll
    for (int mi = 0; mi < 4; mi++)
#pragma unroll
        for (int ni = 0; ni < 4; ni++)
#pragma unroll
            for (int r = 0; r < 4; r++) acc[mi][ni][r] = 0.0f;

    issue_stage(0, 0);

    // ldmatrix per-lane base offsets (halves)
    const uint32_t aoff0 = (uint32_t)((warp_m * 64 + lr + (lm & 1) * 8) * GSTR
                                      + (lm >> 1) * 8) * 2;
    const uint32_t boff0 = (uint32_t)((warp_n * 32 + lr + (lm >> 1) * 8) * GSTR
                                      + (lm & 1) * 8) * 2;

    for (int it = 0; it < GNCHUNK; ++it) {
        if (it + 1 < GNCHUNK) issue_stage(it + 1, (it + 1) & 1);
        else asm volatile("cp.async.commit_group;" ::: "memory");
        asm volatile("cp.async.wait_group 1;" ::: "memory");
        __syncthreads();

        const uint32_t stage = smb + (uint32_t)(it & 1) * 2 * GTILE_B;
        const uint32_t aBase = stage + aoff0;
        const uint32_t bBase = stage + GTILE_B + boff0;

#pragma unroll
        for (int j = 0; j < 4; j++) {           // k16 slices
            uint32_t aa[4][4], bb[2][4];
#pragma unroll
            for (int mi = 0; mi < 4; mi++)
                ldsm_x4(aa[mi], aBase + (uint32_t)(mi * 16 * GSTR + j * 16) * 2);
#pragma unroll
            for (int np = 0; np < 2; np++)
                ldsm_x4(bb[np], bBase + (uint32_t)(np * 16 * GSTR + j * 16) * 2);
#pragma unroll
            for (int mi = 0; mi < 4; mi++)
#pragma unroll
                for (int ni = 0; ni < 4; ni++)
                    mma_f16(acc[mi][ni][0], acc[mi][ni][1],
                            acc[mi][ni][2], acc[mi][ni][3],
                            aa[mi][0], aa[mi][1], aa[mi][2], aa[mi][3],
                            bb[ni >> 1][(ni & 1) * 2], bb[ni >> 1][(ni & 1) * 2 + 1]);
        }
        __syncthreads();
    }

#pragma unroll
    for (int mi = 0; mi < 4; mi++) {
        const int row = blockIdx.y * 128 + warp_m * 64 + mi * 16 + grp;
#pragma unroll
        for (int ni = 0; ni < 4; ni++) {
            const int col = blockIdx.x * 128 + warp_n * 32 + ni * 8 + qid * 2;
            if (HOUT) {
                __half* C = (__half*)Cv;
                *(uint32_t*)&C[(size_t)row * D_SZ + col] =
                    pack2h(acc[mi][ni][0], acc[mi][ni][1]);
                *(uint32_t*)&C[(size_t)(row + 8) * D_SZ + col] =
                    pack2h(acc[mi][ni][2], acc[mi][ni][3]);
            } else {
                float* C = (float*)Cv;
                *(float2*)&C[(size_t)row * D_SZ + col] =
                    make_float2(acc[mi][ni][0], acc[mi][ni][1]);
                *(float2*)&C[(size_t)(row + 8) * D_SZ + col] =
                    make_float2(acc[mi][ni][2], acc[mi][ni][3]);
            }
        }
    }
}

// ---------------------------------------------------------------------------
// RoPE on fp16 pairs (rotate in fp32, RN back to fp16); scale folded into Q
// ---------------------------------------------------------------------------
__global__ void rope_kernel(__half2* __restrict__ t,
                            const float* __restrict__ fcos,
                            const float* __restrict__ fsin,
                            float scale)
{
    int idx = blockIdx.x * blockDim.x + threadIdx.x;
    const int pairs = (int)(NELEM / 2);
    if (idx >= pairs) return;
    int i = idx & (HD_S / 2 - 1);
    int l = (idx / (D_SZ / 2)) % L_SZ;
    float c = fcos[l * (HD_S / 2) + i];
    float s = fsin[l * (HD_S / 2) + i];
    float2 v = __half22float2(t[idx]);
    t[idx] = __floats2half2_rn((v.x * c - v.y * s) * scale,
                               (v.x * s + v.y * c) * scale);
}

// ---------------------------------------------------------------------------
// Flash attention, fp16 mma.sync.m16n8k16.
// 256 thr (8 warps), Q tile 128 rows (warp w: rows 16w..16w+15), KV tiles 64.
// Q frags preloaded to regs; K via ldmatrix; V via ldmatrix.trans;
// P stays in registers (S-accum layout == A-frag layout after f16 pack).
// Smem rows stride 136 halves (272B): bank start 4r mod 32 -> conflict-free.
// ---------------------------------------------------------------------------
#define ASTR 136
#define ATT_SMEM_B ((128 + 64 + 64) * ASTR * 2)   // 69632 B

__global__ __launch_bounds__(256, 1) void attn_f16(const __half* __restrict__ Q,
                                                   const __half* __restrict__ Kg,
                                                   const __half* __restrict__ Vg,
                                                   __half* __restrict__ Og)
{
    extern __shared__ __half smh[];
    __half* Qs = smh;                    // [128][136]
    __half* Ks = Qs + 128 * ASTR;        // [64][136]
    __half* Vs = Ks + 64 * ASTR;         // [64][136]
    const uint32_t qsb = smem_u32(Qs), ksb = smem_u32(Ks), vsb = smem_u32(Vs);

    const int tid = threadIdx.x, lane = tid & 31, wid = tid >> 5;
    const int grp = lane >> 2, qid = lane & 3;
    const int lm = lane >> 3, lr = lane & 7;
    const int bh = blockIdx.y, b = bh >> 5, h = bh & 31;
    const int q0 = blockIdx.x * 128;
    const size_t rowbase = (size_t)b * L_SZ;
    const size_t col0 = (size_t)h * HD_S;
    const int m0 = wid * 16;

    // --- load Q tile, then preload all Q fragments to registers ---
    {
        const __half* Qg = Q + (rowbase + q0) * D_SZ + col0;
#pragma unroll
        for (int i = 0; i < 8; i++) {
            const int u = tid + 256 * i, row = u >> 4, c = u & 15;
            cp16(qsb + (uint32_t)(row * ASTR + c * 8) * 2, Qg + (size_t)row * D_SZ + c * 8);
        }
        asm volatile("cp.async.commit_group;" ::: "memory");
        asm volatile("cp.async.wait_group 0;" ::: "memory");
        __syncthreads();
    }
    uint32_t qa[8][4];
    {
        const uint32_t aoff = qsb + (uint32_t)((m0 + lr + (lm & 1) * 8) * ASTR
                                               + (lm >> 1) * 8) * 2;
#pragma unroll
        for (int j = 0; j < 8; j++) ldsm_x4(qa[j], aoff + (uint32_t)(j * 16) * 2);
    }

    const uint32_t koff = ksb + (uint32_t)((lr + (lm >> 1) * 8) * ASTR + (lm & 1) * 8) * 2;
    const uint32_t voff = vsb + (uint32_t)((lr + (lm & 1) * 8) * ASTR + (lm >> 1) * 8) * 2;

    float m_lo = -1e30f, m_hi = -1e30f, l_lo = 0.0f, l_hi = 0.0f;
    float o[16][4];
#pragma unroll
    for (int nb = 0; nb < 16; nb++)
#pragma unroll
        for (int r = 0; r < 4; r++) o[nb][r] = 0.0f;

    for (int kv = 0; kv < L_SZ; kv += 64) {
        const __half* Kt = Kg + (rowbase + kv) * D_SZ + col0;
        const __half* Vt = Vg + (rowbase + kv) * D_SZ + col0;
#pragma unroll
        for (int i = 0; i < 8; i++) {
            const int u = tid + 256 * i;
            const int v = u & 1023;
            const int row = v >> 4, c = v & 15;
            const uint32_t so = (uint32_t)(row * ASTR + c * 8) * 2;
            if (u < 1024) cp16(ksb + so, Kt + (size_t)row * D_SZ + c * 8);
            else          cp16(vsb + so, Vt + (size_t)row * D_SZ + c * 8);
        }
        asm volatile("cp.async.commit_group;" ::: "memory");
        asm volatile("cp.async.wait_group 0;" ::: "memory");
        __syncthreads();

        // ---- S = Q K^T : m16 x n64, K=128 (8 k16-slices) ----
        float s[8][4];
#pragma unroll
        for (int nb = 0; nb < 8; nb++)
#pragma unroll
            for (int r = 0; r < 4; r++) s[nb][r] = 0.0f;

#pragma unroll
        for (int j = 0; j < 8; j++) {
            uint32_t bb[4][4];
#pragma unroll
            for (int np = 0; np < 4; np++)
                ldsm_x4(bb[np], koff + (uint32_t)(np * 16 * ASTR + j * 16) * 2);
#pragma unroll
            for (int nb = 0; nb < 8; nb++)
                mma_f16(s[nb][0], s[nb][1], s[nb][2], s[nb][3],
                        qa[j][0], qa[j][1], qa[j][2], qa[j][3],
                        bb[nb >> 1][(nb & 1) * 2], bb[nb >> 1][(nb & 1) * 2 + 1]);
        }

        // ---- online softmax (rows grp / grp+8); P packed to fp16 in regs ----
        float tl = -1e30f, th = -1e30f;
#pragma unroll
        for (int nb = 0; nb < 8; nb++) {
            tl = fmaxf(tl, fmaxf(s[nb][0], s[nb][1]));
            th = fmaxf(th, fmaxf(s[nb][2], s[nb][3]));
        }
        tl = fmaxf(tl, __shfl_xor_sync(0xffffffffu, tl, 1));
        tl = fmaxf(tl, __shfl_xor_sync(0xffffffffu, tl, 2));
        th = fmaxf(th, __shfl_xor_sync(0xffffffffu, th, 1));
        th = fmaxf(th, __shfl_xor_sync(0xffffffffu, th, 2));
        const float mnl = fmaxf(m_lo, tl), mnh = fmaxf(m_hi, th);
        const float cl = __expf(m_lo - mnl), ch = __expf(m_hi - mnh);

        uint32_t ph[8][2];
        float rl = 0.0f, rh = 0.0f;
#pragma unroll
        for (int nb = 0; nb < 8; nb++) {
            ph[nb][0] = pack2h(__expf(s[nb][0] - mnl), __expf(s[nb][1] - mnl));
            ph[nb][1] = pack2h(__expf(s[nb][2] - mnh), __expf(s[nb][3] - mnh));
            float2 f0 = __half22float2(*(__half2*)&ph[nb][0]);
            float2 f1 = __half22float2(*(__half2*)&ph[nb][1]);
            rl += f0.x + f0.y;
            rh += f1.x + f1.y;
        }
        rl += __shfl_xor_sync(0xffffffffu, rl, 1);
        rl += __shfl_xor_sync(0xffffffffu, rl, 2);
        rh += __shfl_xor_sync(0xffffffffu, rh, 1);
        rh += __shfl_xor_sync(0xffffffffu, rh, 2);
        l_lo = l_lo * cl + rl; m_lo = mnl;
        l_hi = l_hi * ch + rh; m_hi = mnh;
#pragma unroll
        for (int nb = 0; nb < 16; nb++) {
            o[nb][0] *= cl; o[nb][1] *= cl;
            o[nb][2] *= ch; o[nb][3] *= ch;
        }

        // ---- O += P V : m16 x n128, K=64 (4 k16-slices); V via ldsm.trans ----
#pragma unroll
        for (int js = 0; js < 4; js++) {
            const uint32_t pa0 = ph[2 * js][0],     pa1 = ph[2 * js][1];
            const uint32_t pa2 = ph[2 * js + 1][0], pa3 = ph[2 * js + 1][1];
#pragma unroll
            for (int dp = 0; dp < 8; dp++) {
                uint32_t bb[4];
                ldsm_x4t(bb, voff + (uint32_t)(js * 16 * ASTR + dp * 16) * 2);
                mma_f16(o[2 * dp][0], o[2 * dp][1], o[2 * dp][2], o[2 * dp][3],
                        pa0, pa1, pa2, pa3, bb[0], bb[1]);
                mma_f16(o[2 * dp + 1][0], o[2 * dp + 1][1],
                        o[2 * dp + 1][2], o[2 * dp + 1][3],
                        pa0, pa1, pa2, pa3, bb[2], bb[3]);
            }
        }
        __syncthreads();   // protect Ks/Vs for next iteration
    }

    // epilogue: normalize, fp16 out (consumed by final GEMM)
    const float il = 1.0f / l_lo, ih = 1.0f / l_hi;
    const size_t row_lo = rowbase + q0 + m0 + grp;
    const size_t row_hi = row_lo + 8;
#pragma unroll
    for (int nb = 0; nb < 16; nb++) {
        const size_t col = col0 + 8 * nb + 2 * qid;
        *(uint32_t*)&Og[row_lo * D_SZ + col] = pack2h(o[nb][0] * il, o[nb][1] * il);
        *(uint32_t*)&Og[row_hi * D_SZ + col] = pack2h(o[nb][2] * ih, o[nb][3] * ih);
    }
}

// ---------------------------------------------------------------------------
// Launch. 0-indexed launch #3 (ncu's effective skip) = gemm_f16.
// ---------------------------------------------------------------------------
extern "C" void kernel_launch(void* const* d_in, const int* in_sizes, int n_in,
                              void* d_out, int out_size)
{
    (void)in_sizes; (void)n_in; (void)out_size;
    const float* x    = (const float*)d_in[0];
    const float* fcos = (const float*)d_in[1];
    const float* fsin = (const float*)d_in[2];
    const float* Wq   = (const float*)d_in[3];
    const float* Wk   = (const float*)d_in[4];
    const float* Wv   = (const float*)d_in[5];
    const float* Wo   = (const float*)d_in[6];
    float* out = (float*)d_out;

    __half *Qb, *Kb, *Vb, *Ab, *Xc, *Wqc, *Wkc, *Wvc, *Woc;
    cudaGetSymbolAddress((void**)&Qb, g_Q);
    cudaGetSymbolAddress((void**)&Kb, g_K);
    cudaGetSymbolAddress((void**)&Vb, g_V);
    cudaGetSymbolAddress((void**)&Ab, g_A);
    cudaGetSymbolAddress((void**)&Xc, g_Xc);
    cudaGetSymbolAddress((void**)&Wqc, g_Wqc);
    cudaGetSymbolAddress((void**)&Wkc, g_Wkc);
    cudaGetSymbolAddress((void**)&Wvc, g_Wvc);
    cudaGetSymbolAddress((void**)&Woc, g_Woc);

    const size_t GEMM_SMEM = 4 * GTILE_B;   // 73728 B
    cudaFuncSetAttribute(gemm_f16<true>, cudaFuncAttributeMaxDynamicSharedMemorySize,
                         (int)GEMM_SMEM);
    cudaFuncSetAttribute(gemm_f16<false>, cudaFuncAttributeMaxDynamicSharedMemorySize,
                         (int)GEMM_SMEM);
    cudaFuncSetAttribute(attn_f16, cudaFuncAttributeMaxDynamicSharedMemorySize,
                         ATT_SMEM_B);

    dim3 gg(D_SZ / 128, M_ROWS / 128);

    // 0: fused fp16 conversion (x + all weights)
    {
        const int groups = (int)(NELEM / 8);
        dim3 cg((groups + 255) / 256, 5);
        cvt_f16_fused<<<cg, 256>>>(x, Wq, Wk, Wv, Wo, Xc, Wqc, Wkc, Wvc, Woc);
    }

    // 1-3: projections (launch #3 = gemm -> ncu profiles it)
    gemm_f16<true><<<gg, 256, GEMM_SMEM>>>(Xc, Wqc, Qb);
    gemm_f16<true><<<gg, 256, GEMM_SMEM>>>(Xc, Wkc, Kb);
    gemm_f16<true><<<gg, 256, GEMM_SMEM>>>(Xc, Wvc, Vb);

    // 4-5: rope (fp16 in/out; scale folded into Q)
    const int pairs = (int)(NELEM / 2);
    const float qscale = 0.08838834764831845f;  // 1/sqrt(128)
    rope_kernel<<<(pairs + 255) / 256, 256>>>((__half2*)Qb, fcos, fsin, qscale);
    rope_kernel<<<(pairs + 255) / 256, 256>>>((__half2*)Kb, fcos, fsin, 1.0f);

    // 6: attention
    attn_f16<<<dim3(L_SZ / 128, B_SZ * H_N), 256, ATT_SMEM_B>>>(Qb, Kb, Vb, Ab);

    // 7: output projection (fp32 out)
    gemm_f16<false><<<gg, 256, GEMM_SMEM>>>(Ab, Woc, out);
}

// round 9
// speedup vs baseline: 7.8716x; 1.0506x over previous
#include <cuda_runtime.h>
#include <cuda_fp16.h>
#include <cstdint>
#include <math.h>

// Problem constants
#define B_SZ 2
#define L_SZ 2048
#define D_SZ 4096
#define H_N  32
#define HD_S 128
#define M_ROWS (B_SZ * L_SZ)   // 4096
#define NELEM ((size_t)M_ROWS * D_SZ)

// ---------------------------------------------------------------------------
// Scratch (device globals; fp16 intermediates)
// ---------------------------------------------------------------------------
__device__ __align__(256) __half g_Q[NELEM];
__device__ __align__(256) __half g_K[NELEM];
__device__ __align__(256) __half g_V[NELEM];
__device__ __align__(256) __half g_A[NELEM];
__device__ __align__(256) __half g_Xc[NELEM];
__device__ __align__(256) __half g_Wqc[NELEM];
__device__ __align__(256) __half g_Wkc[NELEM];
__device__ __align__(256) __half g_Wvc[NELEM];
__device__ __align__(256) __half g_Woc[NELEM];

// ---------------------------------------------------------------------------
// Helpers
// ---------------------------------------------------------------------------
__device__ __forceinline__ uint32_t smem_u32(const void* p) {
    uint32_t a;
    asm("{ .reg .u64 t; cvta.to.shared.u64 t, %1; cvt.u32.u64 %0, t; }"
        : "=r"(a) : "l"(p));
    return a;
}
__device__ __forceinline__ void cp16(uint32_t saddr, const void* gaddr) {
    asm volatile("cp.async.cg.shared.global [%0], [%1], 16;" :: "r"(saddr), "l"(gaddr));
}
__device__ __forceinline__ void ldsm_x4(uint32_t* r, uint32_t addr) {
    asm volatile("ldmatrix.sync.aligned.m8n8.x4.shared.b16 {%0,%1,%2,%3}, [%4];"
                 : "=r"(r[0]), "=r"(r[1]), "=r"(r[2]), "=r"(r[3]) : "r"(addr));
}
__device__ __forceinline__ void ldsm_x4t(uint32_t* r, uint32_t addr) {
    asm volatile("ldmatrix.sync.aligned.m8n8.x4.trans.shared.b16 {%0,%1,%2,%3}, [%4];"
                 : "=r"(r[0]), "=r"(r[1]), "=r"(r[2]), "=r"(r[3]) : "r"(addr));
}
__device__ __forceinline__ void mma_f16(float& c0, float& c1, float& c2, float& c3,
                                        uint32_t a0, uint32_t a1, uint32_t a2, uint32_t a3,
                                        uint32_t b0, uint32_t b1) {
    asm volatile(
        "mma.sync.aligned.m16n8k16.row.col.f32.f16.f16.f32 "
        "{%0,%1,%2,%3}, {%4,%5,%6,%7}, {%8,%9}, {%0,%1,%2,%3};"
        : "+f"(c0), "+f"(c1), "+f"(c2), "+f"(c3)
        : "r"(a0), "r"(a1), "r"(a2), "r"(a3), "r"(b0), "r"(b1));
}
__device__ __forceinline__ uint32_t pack2h(float a, float b) {
    __half2 h = __floats2half2_rn(a, b);
    return *(uint32_t*)&h;
}

// ---------------------------------------------------------------------------
// Fused fp32->fp16 (RN) conversion of x + 4 weights (1 launch)
// ---------------------------------------------------------------------------
__global__ void cvt_f16_fused(const float* __restrict__ x,  const float* __restrict__ wq,
                              const float* __restrict__ wk, const float* __restrict__ wv,
                              const float* __restrict__ wo,
                              __half* xc, __half* wqc, __half* wkc, __half* wvc, __half* woc)
{
    const float* src; __half* dst;
    switch (blockIdx.y) {
        case 0: src = x;  dst = xc;  break;
        case 1: src = wq; dst = wqc; break;
        case 2: src = wk; dst = wkc; break;
        case 3: src = wv; dst = wvc; break;
        default: src = wo; dst = woc; break;
    }
    size_t i = (size_t)blockIdx.x * blockDim.x + threadIdx.x;   // 8-elt groups
    if (i >= NELEM / 8) return;
    float4 v0 = ((const float4*)src)[2 * i];
    float4 v1 = ((const float4*)src)[2 * i + 1];
    uint4 o;
    o.x = pack2h(v0.x, v0.y); o.y = pack2h(v0.z, v0.w);
    o.z = pack2h(v1.x, v1.y); o.w = pack2h(v1.z, v1.w);
    ((uint4*)dst)[i] = o;
}

// ---------------------------------------------------------------------------
// fp16 GEMM core: 128x128 CTA tile, BK=64, 8 warps (2x4), warp tile 64x32,
// 3-stage cp.async pipeline, ldmatrix fragments, stride-72-half smem rows.
// ---------------------------------------------------------------------------
#define GSTR 72
#define GTILE_B (128 * GSTR * 2)     // 18432 B per operand per stage
#define GNCHUNK (D_SZ / 64)          // 64
#define GSMEM (6 * GTILE_B)          // 110592 B (3 stages x 2 operands)

struct GemmCore {
    uint32_t smb;
    int lane, wid, warp_m, warp_n, grp, qid, lm, lr;
    const __half *Ag, *Bg;
    float acc[4][4][4];
    uint32_t aoff0, boff0;
    int tid;

    __device__ __forceinline__ void init(uint32_t smb_, int tid_,
                                         const __half* Ag_, const __half* Bg_) {
        smb = smb_; tid = tid_;
        lane = tid & 31; wid = tid >> 5;
        warp_m = wid >> 2; warp_n = wid & 3;
        grp = lane >> 2; qid = lane & 3;
        lm = lane >> 3; lr = lane & 7;
        Ag = Ag_; Bg = Bg_;
#pragma unroll
        for (int mi = 0; mi < 4; mi++)
#pragma unroll
            for (int ni = 0; ni < 4; ni++)
#pragma unroll
                for (int r = 0; r < 4; r++) acc[mi][ni][r] = 0.0f;
        aoff0 = (uint32_t)((warp_m * 64 + lr + (lm & 1) * 8) * GSTR + (lm >> 1) * 8) * 2;
        boff0 = (uint32_t)((warp_n * 32 + lr + (lm >> 1) * 8) * GSTR + (lm & 1) * 8) * 2;
    }

    __device__ __forceinline__ void issue_stage(int it, int s) {
        const int k0 = it * 64;
        const uint32_t base = smb + (uint32_t)s * 2 * GTILE_B;
#pragma unroll
        for (int i = 0; i < 8; i++) {
            const int u = tid + 256 * i;
            const int v = u & 1023;
            const int row = v >> 3, c = v & 7;
            const uint32_t so = (uint32_t)(row * GSTR + c * 8) * 2;
            if (u < 1024)
                cp16(base + so, Ag + (size_t)row * D_SZ + k0 + c * 8);
            else
                cp16(base + GTILE_B + so, Bg + (size_t)row * D_SZ + k0 + c * 8);
        }
        asm volatile("cp.async.commit_group;" ::: "memory");
    }

    __device__ __forceinline__ void run() {
        issue_stage(0, 0);
        issue_stage(1, 1);
        int s = 0;                     // stage of chunk `it` (it % 3)
        for (int it = 0; it < GNCHUNK; ++it) {
            if (it + 2 < GNCHUNK) {
                int s2 = s + 2; if (s2 >= 3) s2 -= 3;
                issue_stage(it + 2, s2);
            } else {
                asm volatile("cp.async.commit_group;" ::: "memory");
            }
            asm volatile("cp.async.wait_group 2;" ::: "memory");
            __syncthreads();

            const uint32_t stage = smb + (uint32_t)s * 2 * GTILE_B;
            const uint32_t aBase = stage + aoff0;
            const uint32_t bBase = stage + GTILE_B + boff0;
#pragma unroll
            for (int j = 0; j < 4; j++) {
                uint32_t aa[4][4], bb[2][4];
#pragma unroll
                for (int mi = 0; mi < 4; mi++)
                    ldsm_x4(aa[mi], aBase + (uint32_t)(mi * 16 * GSTR + j * 16) * 2);
#pragma unroll
                for (int np = 0; np < 2; np++)
                    ldsm_x4(bb[np], bBase + (uint32_t)(np * 16 * GSTR + j * 16) * 2);
#pragma unroll
                for (int mi = 0; mi < 4; mi++)
#pragma unroll
                    for (int ni = 0; ni < 4; ni++)
                        mma_f16(acc[mi][ni][0], acc[mi][ni][1],
                                acc[mi][ni][2], acc[mi][ni][3],
                                aa[mi][0], aa[mi][1], aa[mi][2], aa[mi][3],
                                bb[ni >> 1][(ni & 1) * 2], bb[ni >> 1][(ni & 1) * 2 + 1]);
            }
            __syncthreads();
            if (++s == 3) s = 0;
        }
    }
};

// QKV fused: grid (96, 32); bx>>5 selects weight/output
__global__ __launch_bounds__(256, 2) void gemm_qkv(const __half* __restrict__ X,
                                                   const __half* __restrict__ Wq,
                                                   const __half* __restrict__ Wk,
                                                   const __half* __restrict__ Wv,
                                                   __half* __restrict__ Qo,
                                                   __half* __restrict__ Ko,
                                                   __half* __restrict__ Vo)
{
    extern __shared__ __half smh[];
    const int sel = blockIdx.x >> 5, nx = blockIdx.x & 31;
    const __half* Bw = (sel == 0) ? Wq : (sel == 1) ? Wk : Wv;
    __half* C = (sel == 0) ? Qo : (sel == 1) ? Ko : Vo;

    GemmCore g;
    g.init(smem_u32(smh), threadIdx.x,
           X + (size_t)(blockIdx.y * 128) * D_SZ,
           Bw + (size_t)(nx * 128) * D_SZ);
    g.run();

#pragma unroll
    for (int mi = 0; mi < 4; mi++) {
        const int row = blockIdx.y * 128 + g.warp_m * 64 + mi * 16 + g.grp;
#pragma unroll
        for (int ni = 0; ni < 4; ni++) {
            const int col = nx * 128 + g.warp_n * 32 + ni * 8 + g.qid * 2;
            *(uint32_t*)&C[(size_t)row * D_SZ + col] =
                pack2h(g.acc[mi][ni][0], g.acc[mi][ni][1]);
            *(uint32_t*)&C[(size_t)(row + 8) * D_SZ + col] =
                pack2h(g.acc[mi][ni][2], g.acc[mi][ni][3]);
        }
    }
}

// Single GEMM, fp32 output (final Wo projection)
__global__ __launch_bounds__(256, 2) void gemm_f32out(const __half* __restrict__ A,
                                                      const __half* __restrict__ Bw,
                                                      float* __restrict__ C)
{
    extern __shared__ __half smh[];
    GemmCore g;
    g.init(smem_u32(smh), threadIdx.x,
           A + (size_t)(blockIdx.y * 128) * D_SZ,
           Bw + (size_t)(blockIdx.x * 128) * D_SZ);
    g.run();

#pragma unroll
    for (int mi = 0; mi < 4; mi++) {
        const int row = blockIdx.y * 128 + g.warp_m * 64 + mi * 16 + g.grp;
#pragma unroll
        for (int ni = 0; ni < 4; ni++) {
            const int col = blockIdx.x * 128 + g.warp_n * 32 + ni * 8 + g.qid * 2;
            *(float2*)&C[(size_t)row * D_SZ + col] =
                make_float2(g.acc[mi][ni][0], g.acc[mi][ni][1]);
            *(float2*)&C[(size_t)(row + 8) * D_SZ + col] =
                make_float2(g.acc[mi][ni][2], g.acc[mi][ni][3]);
        }
    }
}

// ---------------------------------------------------------------------------
// Fused RoPE on Q and K (grid.y selects; scale folded into Q)
// ---------------------------------------------------------------------------
__global__ void rope_fused(__half2* __restrict__ q, __half2* __restrict__ k,
                           const float* __restrict__ fcos,
                           const float* __restrict__ fsin)
{
    int idx = blockIdx.x * blockDim.x + threadIdx.x;
    const int pairs = (int)(NELEM / 2);
    if (idx >= pairs) return;
    __half2* t = blockIdx.y ? k : q;
    const float scale = blockIdx.y ? 1.0f : 0.08838834764831845f;
    int i = idx & (HD_S / 2 - 1);
    int l = (idx / (D_SZ / 2)) % L_SZ;
    float c = fcos[l * (HD_S / 2) + i];
    float s = fsin[l * (HD_S / 2) + i];
    float2 v = __half22float2(t[idx]);
    t[idx] = __floats2half2_rn((v.x * c - v.y * s) * scale,
                               (v.x * s + v.y * c) * scale);
}

// ---------------------------------------------------------------------------
// Flash attention, fp16 mma.sync.m16n8k16, double-buffered KV tiles.
// 256 thr (8 warps), Q tile 128 rows (warp w: rows 16w..16w+15), KV tiles 64.
// Smem: Qs[128][136] + 2x (Ks[64][136], Vs[64][136]) = 104448 B.
// ---------------------------------------------------------------------------
#define ASTR 136
#define AKV_H (128 * ASTR)                    // halves per KV stage (K+V)
#define ATT_SMEM_B ((128 * ASTR + 2 * AKV_H) * 2)   // 104448 B

__global__ __launch_bounds__(256, 1) void attn_f16(const __half* __restrict__ Q,
                                                   const __half* __restrict__ Kg,
                                                   const __half* __restrict__ Vg,
                                                   __half* __restrict__ Og)
{
    extern __shared__ __half smh[];
    const uint32_t qsb = smem_u32(smh);                    // Q [128][136]
    const uint32_t kv0 = qsb + (uint32_t)(128 * ASTR) * 2; // stage bases (bytes)

    const int tid = threadIdx.x, lane = tid & 31, wid = tid >> 5;
    const int grp = lane >> 2, qid = lane & 3;
    const int lm = lane >> 3, lr = lane & 7;
    const int bh = blockIdx.y, b = bh >> 5, h = bh & 31;
    const int q0 = blockIdx.x * 128;
    const size_t rowbase = (size_t)b * L_SZ;
    const size_t col0 = (size_t)h * HD_S;
    const int m0 = wid * 16;

    const __half* Kbase = Kg + rowbase * D_SZ + col0;
    const __half* Vbase = Vg + rowbase * D_SZ + col0;

    auto issue_kv = [&](int kvi, int s) {
        const __half* Kt = Kbase + (size_t)(kvi * 64) * D_SZ;
        const __half* Vt = Vbase + (size_t)(kvi * 64) * D_SZ;
        const uint32_t kb = kv0 + (uint32_t)s * AKV_H * 2;
        const uint32_t vb = kb + (uint32_t)(64 * ASTR) * 2;
#pragma unroll
        for (int i = 0; i < 8; i++) {
            const int u = tid + 256 * i;
            const int v = u & 1023;
            const int row = v >> 4, c = v & 15;
            const uint32_t so = (uint32_t)(row * ASTR + c * 8) * 2;
            if (u < 1024) cp16(kb + so, Kt + (size_t)row * D_SZ + c * 8);
            else          cp16(vb + so, Vt + (size_t)row * D_SZ + c * 8);
        }
        asm volatile("cp.async.commit_group;" ::: "memory");
    };

    // prologue: Q tile (group 0), KV tile 0 (group 1)
    {
        const __half* Qg = Q + (rowbase + q0) * D_SZ + col0;
#pragma unroll
        for (int i = 0; i < 8; i++) {
            const int u = tid + 256 * i, row = u >> 4, c = u & 15;
            cp16(qsb + (uint32_t)(row * ASTR + c * 8) * 2, Qg + (size_t)row * D_SZ + c * 8);
        }
        asm volatile("cp.async.commit_group;" ::: "memory");
    }
    issue_kv(0, 0);
    asm volatile("cp.async.wait_group 1;" ::: "memory");   // Q ready
    __syncthreads();

    // preload Q fragments
    uint32_t qa[8][4];
    {
        const uint32_t aoff = qsb + (uint32_t)((m0 + lr + (lm & 1) * 8) * ASTR
                                               + (lm >> 1) * 8) * 2;
#pragma unroll
        for (int j = 0; j < 8; j++) ldsm_x4(qa[j], aoff + (uint32_t)(j * 16) * 2);
    }

    const uint32_t koffrel = (uint32_t)((lr + (lm >> 1) * 8) * ASTR + (lm & 1) * 8) * 2;
    const uint32_t voffrel = (uint32_t)((lr + (lm & 1) * 8) * ASTR + (lm >> 1) * 8) * 2;

    float m_lo = -1e30f, m_hi = -1e30f, l_lo = 0.0f, l_hi = 0.0f;
    float o[16][4];
#pragma unroll
    for (int nb = 0; nb < 16; nb++)
#pragma unroll
        for (int r = 0; r < 4; r++) o[nb][r] = 0.0f;

    const int NT = L_SZ / 64;   // 32 tiles
    for (int it = 0; it < NT; ++it) {
        if (it + 1 < NT) {
            issue_kv(it + 1, (it + 1) & 1);
            asm volatile("cp.async.wait_group 1;" ::: "memory");
        } else {
            asm volatile("cp.async.wait_group 0;" ::: "memory");
        }
        __syncthreads();

        const uint32_t kb = kv0 + (uint32_t)(it & 1) * AKV_H * 2;
        const uint32_t koff = kb + koffrel;
        const uint32_t voff = kb + (uint32_t)(64 * ASTR) * 2 + voffrel;

        // ---- S = Q K^T : m16 x n64, K=128 (8 k16-slices) ----
        float s[8][4];
#pragma unroll
        for (int nb = 0; nb < 8; nb++)
#pragma unroll
            for (int r = 0; r < 4; r++) s[nb][r] = 0.0f;

#pragma unroll
        for (int j = 0; j < 8; j++) {
            uint32_t bb[4][4];
#pragma unroll
            for (int np = 0; np < 4; np++)
                ldsm_x4(bb[np], koff + (uint32_t)(np * 16 * ASTR + j * 16) * 2);
#pragma unroll
            for (int nb = 0; nb < 8; nb++)
                mma_f16(s[nb][0], s[nb][1], s[nb][2], s[nb][3],
                        qa[j][0], qa[j][1], qa[j][2], qa[j][3],
                        bb[nb >> 1][(nb & 1) * 2], bb[nb >> 1][(nb & 1) * 2 + 1]);
        }

        // ---- online softmax; P packed to fp16 in registers ----
        float tl = -1e30f, th = -1e30f;
#pragma unroll
        for (int nb = 0; nb < 8; nb++) {
            tl = fmaxf(tl, fmaxf(s[nb][0], s[nb][1]));
            th = fmaxf(th, fmaxf(s[nb][2], s[nb][3]));
        }
        tl = fmaxf(tl, __shfl_xor_sync(0xffffffffu, tl, 1));
        tl = fmaxf(tl, __shfl_xor_sync(0xffffffffu, tl, 2));
        th = fmaxf(th, __shfl_xor_sync(0xffffffffu, th, 1));
        th = fmaxf(th, __shfl_xor_sync(0xffffffffu, th, 2));
        const float mnl = fmaxf(m_lo, tl), mnh = fmaxf(m_hi, th);
        const float cl = __expf(m_lo - mnl), ch = __expf(m_hi - mnh);

        uint32_t ph[8][2];
        float rl = 0.0f, rh = 0.0f;
#pragma unroll
        for (int nb = 0; nb < 8; nb++) {
            ph[nb][0] = pack2h(__expf(s[nb][0] - mnl), __expf(s[nb][1] - mnl));
            ph[nb][1] = pack2h(__expf(s[nb][2] - mnh), __expf(s[nb][3] - mnh));
            float2 f0 = __half22float2(*(__half2*)&ph[nb][0]);
            float2 f1 = __half22float2(*(__half2*)&ph[nb][1]);
            rl += f0.x + f0.y;
            rh += f1.x + f1.y;
        }
        rl += __shfl_xor_sync(0xffffffffu, rl, 1);
        rl += __shfl_xor_sync(0xffffffffu, rl, 2);
        rh += __shfl_xor_sync(0xffffffffu, rh, 1);
        rh += __shfl_xor_sync(0xffffffffu, rh, 2);
        l_lo = l_lo * cl + rl; m_lo = mnl;
        l_hi = l_hi * ch + rh; m_hi = mnh;
#pragma unroll
        for (int nb = 0; nb < 16; nb++) {
            o[nb][0] *= cl; o[nb][1] *= cl;
            o[nb][2] *= ch; o[nb][3] *= ch;
        }

        // ---- O += P V : m16 x n128, K=64; V via ldsm.trans ----
#pragma unroll
        for (int js = 0; js < 4; js++) {
            const uint32_t pa0 = ph[2 * js][0],     pa1 = ph[2 * js][1];
            const uint32_t pa2 = ph[2 * js + 1][0], pa3 = ph[2 * js + 1][1];
#pragma unroll
            for (int dp = 0; dp < 8; dp++) {
                uint32_t bb[4];
                ldsm_x4t(bb, voff + (uint32_t)(js * 16 * ASTR + dp * 16) * 2);
                mma_f16(o[2 * dp][0], o[2 * dp][1], o[2 * dp][2], o[2 * dp][3],
                        pa0, pa1, pa2, pa3, bb[0], bb[1]);
                mma_f16(o[2 * dp + 1][0], o[2 * dp + 1][1],
                        o[2 * dp + 1][2], o[2 * dp + 1][3],
                        pa0, pa1, pa2, pa3, bb[2], bb[3]);
            }
        }
        __syncthreads();   // protect this KV buffer before it is re-issued
    }

    // epilogue: normalize, fp16 out (consumed by final GEMM)
    const float il = 1.0f / l_lo, ih = 1.0f / l_hi;
    const size_t row_lo = rowbase + q0 + m0 + grp;
    const size_t row_hi = row_lo + 8;
#pragma unroll
    for (int nb = 0; nb < 16; nb++) {
        const size_t col = col0 + 8 * nb + 2 * qid;
        *(uint32_t*)&Og[row_lo * D_SZ + col] = pack2h(o[nb][0] * il, o[nb][1] * il);
        *(uint32_t*)&Og[row_hi * D_SZ + col] = pack2h(o[nb][2] * ih, o[nb][3] * ih);
    }
}

// ---------------------------------------------------------------------------
// Launch: 0 cvt, 1 qkv-gemm, 2 rope, 3 attn (ncu target), 4 out-gemm
// ---------------------------------------------------------------------------
extern "C" void kernel_launch(void* const* d_in, const int* in_sizes, int n_in,
                              void* d_out, int out_size)
{
    (void)in_sizes; (void)n_in; (void)out_size;
    const float* x    = (const float*)d_in[0];
    const float* fcos = (const float*)d_in[1];
    const float* fsin = (const float*)d_in[2];
    const float* Wq   = (const float*)d_in[3];
    const float* Wk   = (const float*)d_in[4];
    const float* Wv   = (const float*)d_in[5];
    const float* Wo   = (const float*)d_in[6];
    float* out = (float*)d_out;

    __half *Qb, *Kb, *Vb, *Ab, *Xc, *Wqc, *Wkc, *Wvc, *Woc;
    cudaGetSymbolAddress((void**)&Qb, g_Q);
    cudaGetSymbolAddress((void**)&Kb, g_K);
    cudaGetSymbolAddress((void**)&Vb, g_V);
    cudaGetSymbolAddress((void**)&Ab, g_A);
    cudaGetSymbolAddress((void**)&Xc, g_Xc);
    cudaGetSymbolAddress((void**)&Wqc, g_Wqc);
    cudaGetSymbolAddress((void**)&Wkc, g_Wkc);
    cudaGetSymbolAddress((void**)&Wvc, g_Wvc);
    cudaGetSymbolAddress((void**)&Woc, g_Woc);

    cudaFuncSetAttribute(gemm_qkv, cudaFuncAttributeMaxDynamicSharedMemorySize, GSMEM);
    cudaFuncSetAttribute(gemm_f32out, cudaFuncAttributeMaxDynamicSharedMemorySize, GSMEM);
    cudaFuncSetAttribute(attn_f16, cudaFuncAttributeMaxDynamicSharedMemorySize, ATT_SMEM_B);

    // 0: fused fp16 conversion
    {
        const int groups = (int)(NELEM / 8);
        dim3 cg((groups + 255) / 256, 5);
        cvt_f16_fused<<<cg, 256>>>(x, Wq, Wk, Wv, Wo, Xc, Wqc, Wkc, Wvc, Woc);
    }

    // 1: QKV projections (one launch, grid 96x32)
    gemm_qkv<<<dim3(96, 32), 256, GSMEM>>>(Xc, Wqc, Wkc, Wvc, Qb, Kb, Vb);

    // 2: RoPE on Q and K (one launch)
    {
        const int pairs = (int)(NELEM / 2);
        rope_fused<<<dim3((pairs + 255) / 256, 2), 256>>>((__half2*)Qb, (__half2*)Kb,
                                                          fcos, fsin);
    }

    // 3: attention
    attn_f16<<<dim3(L_SZ / 128, B_SZ * H_N), 256, ATT_SMEM_B>>>(Qb, Kb, Vb, Ab);

    // 4: output projection (fp32 out)
    gemm_f32out<<<dim3(D_SZ / 128, M_ROWS / 128), 256, GSMEM>>>(Ab, Woc, out);
}